// round 2
// baseline (speedup 1.0000x reference)
#include <cuda_runtime.h>
#include <math.h>

// Problem constants
constexpr int B   = 8;
constexpr int S   = 1024;
constexpr int D   = 1024;
constexpr int H   = 16;
constexpr int DK  = 64;
constexpr int DFF = 4096;
constexpr int NT  = B * S;          // 8192 rows
constexpr float EPS = 1e-5f;

// ---------------------------------------------------------------------------
// Scratch (static __device__ arrays — no runtime allocation)
// ---------------------------------------------------------------------------
__device__ float g_q  [NT * D];
__device__ float g_k  [NT * D];
__device__ float g_v  [NT * D];
__device__ float g_ctx[NT * D];
__device__ float g_h  [NT * D];
__device__ float g_ff [(size_t)NT * DFF];
__device__ float g_part[2 * B * 256];
__device__ float g_stats[2 * B];

// ---------------------------------------------------------------------------
// SGEMM: C[M,N] = A[M,K] * W[K,N] + bias[N] (+ epilogue)
// EPI: 0 = bias only, 1 = bias + exact GeLU, 2 = bias + residual add
// BM=BN=128, BK=8, 256 threads, 8x8 per-thread microtile
// ---------------------------------------------------------------------------
#define BM 128
#define BN 128
#define BKK 8
#define TM 8
#define TN 8

template <int EPI>
__global__ void __launch_bounds__(256)
sgemm_kernel(const float* __restrict__ A, const float* __restrict__ W,
             const float* __restrict__ bias, const float* __restrict__ res,
             float* __restrict__ C, int M, int K, int N)
{
    __shared__ float As[BKK][BM];
    __shared__ float Bs[BKK][BN];

    const int bx = blockIdx.x;   // N tile
    const int by = blockIdx.y;   // M tile
    const int tid = threadIdx.x;
    const int tx = tid % 16;
    const int ty = tid / 16;

    float acc[TM][TN];
#pragma unroll
    for (int i = 0; i < TM; i++)
#pragma unroll
        for (int j = 0; j < TN; j++) acc[i][j] = 0.f;

    // A tile load mapping: 256 threads x float4 = 1024 floats (128x8)
    const int arow = tid >> 1;            // 0..127
    const int acol = (tid & 1) * 4;       // 0 or 4
    // B tile load mapping: 8x128
    const int brow = tid >> 5;            // 0..7
    const int bcol = (tid & 31) * 4;      // 0..124

    const float* Aptr = A + (size_t)(by * BM + arow) * K;
    const float* Wptr = W + (size_t)brow * N + bx * BN + bcol;

    for (int k0 = 0; k0 < K; k0 += BKK) {
        float4 av = *(const float4*)(Aptr + k0 + acol);
        As[acol + 0][arow] = av.x;
        As[acol + 1][arow] = av.y;
        As[acol + 2][arow] = av.z;
        As[acol + 3][arow] = av.w;
        float4 bv = *(const float4*)(Wptr + (size_t)k0 * N);
        *(float4*)&Bs[brow][bcol] = bv;
        __syncthreads();

#pragma unroll
        for (int kk = 0; kk < BKK; kk++) {
            float ar[TM], br[TN];
#pragma unroll
            for (int i = 0; i < TM; i++) ar[i] = As[kk][ty * TM + i];
#pragma unroll
            for (int j = 0; j < TN; j++) br[j] = Bs[kk][tx * TN + j];
#pragma unroll
            for (int i = 0; i < TM; i++)
#pragma unroll
                for (int j = 0; j < TN; j++) acc[i][j] += ar[i] * br[j];
        }
        __syncthreads();
    }

#pragma unroll
    for (int i = 0; i < TM; i++) {
        const int row = by * BM + ty * TM + i;
#pragma unroll
        for (int j = 0; j < TN; j++) {
            const int col = bx * BN + tx * TN + j;
            float v = acc[i][j] + bias[col];
            if (EPI == 1) {
                v = 0.5f * v * (1.0f + erff(v * 0.70710678118654752f));
            } else if (EPI == 2) {
                v += res[(size_t)row * N + col];
            }
            C[(size_t)row * N + col] = v;
        }
    }
}

// ---------------------------------------------------------------------------
// Attention: one block per (q row, head, batch). 128 threads.
// scores = (q . K^T)/8 ; softmax ; ctx = p . V
// ---------------------------------------------------------------------------
__global__ void __launch_bounds__(128)
attn_kernel(const float* __restrict__ Q, const float* __restrict__ Kp,
            const float* __restrict__ V, float* __restrict__ O)
{
    __shared__ float q_s[DK];
    __shared__ float sc[S];
    __shared__ float Ks[128][DK + 1];
    __shared__ float red[128];
    __shared__ float part[2][DK];

    const int tid = threadIdx.x;
    const int qi  = blockIdx.x;
    const int hh  = blockIdx.y;
    const int b   = blockIdx.z;

    const float* qrow  = Q  + (size_t)(b * S + qi) * D + hh * DK;
    const float* Kbase = Kp + (size_t)b * S * D + hh * DK;
    const float* Vbase = V  + (size_t)b * S * D + hh * DK;

    if (tid < DK) q_s[tid] = qrow[tid] * 0.125f;   // 1/sqrt(64)
    __syncthreads();

    // scores
    for (int c0 = 0; c0 < S; c0 += 128) {
        for (int idx = tid; idx < 128 * DK; idx += 128) {
            const int r = idx >> 6, d = idx & 63;
            Ks[r][d] = Kbase[(size_t)(c0 + r) * D + d];
        }
        __syncthreads();
        float s = 0.f;
#pragma unroll
        for (int d = 0; d < DK; d++) s += q_s[d] * Ks[tid][d];
        sc[c0 + tid] = s;
        __syncthreads();
    }

    // softmax: max
    float m = -1e30f;
    for (int i = tid; i < S; i += 128) m = fmaxf(m, sc[i]);
    red[tid] = m; __syncthreads();
    for (int st = 64; st > 0; st >>= 1) {
        if (tid < st) red[tid] = fmaxf(red[tid], red[tid + st]);
        __syncthreads();
    }
    const float mx = red[0];
    __syncthreads();

    // exp + sum
    float sum = 0.f;
    for (int i = tid; i < S; i += 128) {
        float e = __expf(sc[i] - mx);
        sc[i] = e;
        sum += e;
    }
    red[tid] = sum; __syncthreads();
    for (int st = 64; st > 0; st >>= 1) {
        if (tid < st) red[tid] += red[tid + st];
        __syncthreads();
    }
    const float inv = 1.0f / red[0];
    __syncthreads();

    // ctx = p . V  (threads split k-range in two halves, d coalesced)
    const int d = tid & 63;
    const int half = tid >> 6;
    float acc = 0.f;
    const float* vp = Vbase + (size_t)(half * 512) * D + d;
    const float* sp = sc + half * 512;
    for (int k = 0; k < 512; k++) acc += sp[k] * vp[(size_t)k * D];
    part[half][d] = acc;
    __syncthreads();

    if (tid < DK)
        O[(size_t)(b * S + qi) * D + hh * DK + tid] =
            (part[0][tid] + part[1][tid]) * inv;
}

// ---------------------------------------------------------------------------
// LayerNorm over (S,D) per batch — stage 1: residual add + partial sums
// grid = (256, B), 256 threads, 16 elems/thread (4096 per block)
// c may be null (no add); y may be null (no store)
// ---------------------------------------------------------------------------
__global__ void __launch_bounds__(256)
ln_partial(const float* __restrict__ a, const float* __restrict__ c,
           float* __restrict__ y, float* __restrict__ part)
{
    const int b = blockIdx.y, chunk = blockIdx.x, tid = threadIdx.x;
    const size_t base = (size_t)b * S * D + (size_t)chunk * 4096 + tid * 16;
    float s = 0.f, s2 = 0.f;
#pragma unroll
    for (int i = 0; i < 16; i += 4) {
        float4 va = *(const float4*)(a + base + i);
        if (c) {
            float4 vc = *(const float4*)(c + base + i);
            va.x += vc.x; va.y += vc.y; va.z += vc.z; va.w += vc.w;
        }
        if (y) *(float4*)(y + base + i) = va;
        s  += va.x + va.y + va.z + va.w;
        s2 += va.x * va.x + va.y * va.y + va.z * va.z + va.w * va.w;
    }
    __shared__ float r1[256], r2[256];
    r1[tid] = s; r2[tid] = s2; __syncthreads();
    for (int st = 128; st > 0; st >>= 1) {
        if (tid < st) { r1[tid] += r1[tid + st]; r2[tid] += r2[tid + st]; }
        __syncthreads();
    }
    if (tid == 0) {
        part[b * 256 + chunk]            = r1[0];
        part[B * 256 + b * 256 + chunk]  = r2[0];
    }
}

// stage 2: finalize mean/rstd per batch
__global__ void __launch_bounds__(256)
ln_finalize(const float* __restrict__ part, float* __restrict__ stats)
{
    const int b = blockIdx.x, tid = threadIdx.x;
    __shared__ float r1[256], r2[256];
    r1[tid] = part[b * 256 + tid];
    r2[tid] = part[B * 256 + b * 256 + tid];
    __syncthreads();
    for (int st = 128; st > 0; st >>= 1) {
        if (tid < st) { r1[tid] += r1[tid + st]; r2[tid] += r2[tid + st]; }
        __syncthreads();
    }
    if (tid == 0) {
        const float n = (float)S * (float)D;
        float mean = r1[0] / n;
        float var  = r2[0] / n - mean * mean;
        stats[2 * b]     = mean;
        stats[2 * b + 1] = rsqrtf(var + EPS);
    }
}

// stage 3: normalize + elementwise (s,d)-indexed affine
// grid = (1024, B), 256 threads, 4 elems/thread
__global__ void __launch_bounds__(256)
ln_apply(const float* __restrict__ y, const float* __restrict__ g,
         const float* __restrict__ beta, const float* __restrict__ stats,
         float* __restrict__ out)
{
    const int b = blockIdx.y;
    const int idx = (blockIdx.x * 256 + threadIdx.x) * 4;    // [0, S*D)
    const float mean = stats[2 * b];
    const float rstd = stats[2 * b + 1];
    const size_t off = (size_t)b * S * D + idx;
    float4 v  = *(const float4*)(y + off);
    float4 gg = *(const float4*)(g + idx);
    float4 bb = *(const float4*)(beta + idx);
    v.x = (v.x - mean) * rstd * gg.x + bb.x;
    v.y = (v.y - mean) * rstd * gg.y + bb.y;
    v.z = (v.z - mean) * rstd * gg.z + bb.z;
    v.w = (v.w - mean) * rstd * gg.w + bb.w;
    *(float4*)(out + off) = v;
}

// ---------------------------------------------------------------------------
// kernel_launch
// ---------------------------------------------------------------------------
extern "C" void kernel_launch(void* const* d_in, const int* in_sizes, int n_in,
                              void* d_out, int out_size)
{
    const float* x    = (const float*)d_in[0];
    const float* wq   = (const float*)d_in[1];
    const float* bq   = (const float*)d_in[2];
    const float* wk   = (const float*)d_in[3];
    const float* bk   = (const float*)d_in[4];
    const float* wv   = (const float*)d_in[5];
    const float* bv   = (const float*)d_in[6];
    const float* ln1g = (const float*)d_in[7];
    const float* ln1b = (const float*)d_in[8];
    const float* w1   = (const float*)d_in[9];
    const float* b1   = (const float*)d_in[10];
    const float* w2   = (const float*)d_in[11];
    const float* b2   = (const float*)d_in[12];
    const float* ln2g = (const float*)d_in[13];
    const float* ln2b = (const float*)d_in[14];
    float* out = (float*)d_out;

    float *q, *k, *v, *ctx, *h, *ff, *part, *stats;
    cudaGetSymbolAddress((void**)&q,     g_q);
    cudaGetSymbolAddress((void**)&k,     g_k);
    cudaGetSymbolAddress((void**)&v,     g_v);
    cudaGetSymbolAddress((void**)&ctx,   g_ctx);
    cudaGetSymbolAddress((void**)&h,     g_h);
    cudaGetSymbolAddress((void**)&ff,    g_ff);
    cudaGetSymbolAddress((void**)&part,  g_part);
    cudaGetSymbolAddress((void**)&stats, g_stats);

    const dim3 gD(D / BN, NT / BM);          // 8 x 64
    const dim3 gF(DFF / BN, NT / BM);        // 32 x 64

    // QKV projections
    sgemm_kernel<0><<<gD, 256>>>(x, wq, bq, nullptr, q, NT, D, D);
    sgemm_kernel<0><<<gD, 256>>>(x, wk, bk, nullptr, k, NT, D, D);
    sgemm_kernel<0><<<gD, 256>>>(x, wv, bv, nullptr, v, NT, D, D);

    // Attention
    attn_kernel<<<dim3(S, H, B), 128>>>(q, k, v, ctx);

    // LayerNorm 1 (joint over (S,D) per batch): h = LN(x + ctx)
    ln_partial<<<dim3(256, B), 256>>>(x, ctx, h, part);
    ln_finalize<<<B, 256>>>(part, stats);
    ln_apply<<<dim3(1024, B), 256>>>(h, ln1g, ln1b, stats, h);

    // FFN: ff = gelu(h @ w1 + b1);  y2 = h + ff @ w2 + b2
    sgemm_kernel<1><<<gF, 256>>>(h, w1, b1, nullptr, ff, NT, D, DFF);
    sgemm_kernel<2><<<gD, 256>>>(ff, w2, b2, h, ctx, NT, DFF, D);

    // LayerNorm 2 -> output
    ln_partial<<<dim3(256, B), 256>>>(ctx, nullptr, nullptr, part);
    ln_finalize<<<B, 256>>>(part, stats);
    ln_apply<<<dim3(1024, B), 256>>>(ctx, ln2g, ln2b, stats, out);
}

// round 3
// speedup vs baseline: 1.2096x; 1.2096x over previous
#include <cuda_runtime.h>
#include <math.h>
#include <stdint.h>

// Problem constants
constexpr int B   = 8;
constexpr int S   = 1024;
constexpr int D   = 1024;
constexpr int H   = 16;
constexpr int DK  = 64;
constexpr int DFF = 4096;
constexpr int NT  = B * S;          // 8192 rows
constexpr float EPS = 1e-5f;

// ---------------------------------------------------------------------------
// Scratch (static __device__ arrays — no runtime allocation)
// ---------------------------------------------------------------------------
__device__ float g_q  [NT * D];
__device__ float g_k  [NT * D];
__device__ float g_v  [NT * D];
__device__ float g_ctx[NT * D];
__device__ float g_h  [NT * D];
__device__ float g_ff [(size_t)NT * DFF];
__device__ float g_part[2 * B * 256];
__device__ float g_stats[2 * B];

// ---------------------------------------------------------------------------
// TF32 tensor-core GEMM: C[M,N] = A[M,K] * W[K,N] + bias[N] (+ epilogue)
// EPI: 0 = bias only, 1 = bias + exact GeLU, 2 = bias + residual add
// BM=BN=128, BK=16, 256 threads (8 warps), warp tile 64x32 via m16n8k8
// ---------------------------------------------------------------------------
__device__ __forceinline__ uint32_t f2tf32(float x) {
    uint32_t r;
    asm("cvt.rna.tf32.f32 %0, %1;" : "=r"(r) : "f"(x));
    return r;
}

__device__ __forceinline__ void mma_tf32(float c[4], const uint32_t a[4], const uint32_t b[2]) {
    asm volatile(
        "mma.sync.aligned.m16n8k8.row.col.f32.tf32.tf32.f32 "
        "{%0,%1,%2,%3}, {%4,%5,%6,%7}, {%8,%9}, {%0,%1,%2,%3};\n"
        : "+f"(c[0]), "+f"(c[1]), "+f"(c[2]), "+f"(c[3])
        : "r"(a[0]), "r"(a[1]), "r"(a[2]), "r"(a[3]), "r"(b[0]), "r"(b[1]));
}

template <int EPI>
__global__ void __launch_bounds__(256)
gemm_tf32(const float* __restrict__ A, const float* __restrict__ W,
          const float* __restrict__ bias, const float* __restrict__ res,
          float* __restrict__ C, int M, int K, int N)
{
    // A tile: row-major [128][16] padded to stride 20 (conflict-free frags)
    // B tile: k-major   [16][128] padded to stride 136 (conflict-free frags)
    __shared__ uint32_t As[128][20];
    __shared__ uint32_t Bs[16][136];

    const int tid  = threadIdx.x;
    const int lane = tid & 31;
    const int warp = tid >> 5;
    const int g    = lane >> 2;   // group id 0..7
    const int t    = lane & 3;    // thread-in-group 0..3
    const int wm   = (warp & 1) * 64;   // warp M offset in tile
    const int wn   = (warp >> 1) * 32;  // warp N offset in tile

    const int bx = blockIdx.x;   // N tile
    const int by = blockIdx.y;   // M tile

    float acc[4][4][4];
#pragma unroll
    for (int mi = 0; mi < 4; mi++)
#pragma unroll
        for (int nj = 0; nj < 4; nj++)
#pragma unroll
            for (int c = 0; c < 4; c++) acc[mi][nj][c] = 0.f;

    const float* Ab = A + (size_t)(by * 128) * K;
    const float* Wb = W + bx * 128;

    for (int k0 = 0; k0 < K; k0 += 16) {
        // ---- stage A tile: 128 rows x 16 k (512 float4, 2 per thread)
#pragma unroll
        for (int u = 0; u < 2; u++) {
            const int i   = tid + u * 256;
            const int row = i >> 2;
            const int kq  = (i & 3) * 4;
            float4 v = *(const float4*)(Ab + (size_t)row * K + k0 + kq);
            uint4 w;
            w.x = f2tf32(v.x); w.y = f2tf32(v.y);
            w.z = f2tf32(v.z); w.w = f2tf32(v.w);
            *(uint4*)&As[row][kq] = w;
        }
        // ---- stage B tile: 16 k x 128 n
#pragma unroll
        for (int u = 0; u < 2; u++) {
            const int i   = tid + u * 256;
            const int row = i >> 5;
            const int c4  = (i & 31) * 4;
            float4 v = *(const float4*)(Wb + (size_t)(k0 + row) * N + c4);
            uint4 w;
            w.x = f2tf32(v.x); w.y = f2tf32(v.y);
            w.z = f2tf32(v.z); w.w = f2tf32(v.w);
            *(uint4*)&Bs[row][c4] = w;
        }
        __syncthreads();

#pragma unroll
        for (int ks = 0; ks < 2; ks++) {
            const int kb = ks * 8;
            uint32_t a[4][4], b[4][2];
#pragma unroll
            for (int mi = 0; mi < 4; mi++) {
                const int m0 = wm + mi * 16;
                a[mi][0] = As[m0 + g    ][kb + t    ];
                a[mi][1] = As[m0 + 8 + g][kb + t    ];
                a[mi][2] = As[m0 + g    ][kb + 4 + t];
                a[mi][3] = As[m0 + 8 + g][kb + 4 + t];
            }
#pragma unroll
            for (int nj = 0; nj < 4; nj++) {
                const int n0 = wn + nj * 8;
                b[nj][0] = Bs[kb + t    ][n0 + g];
                b[nj][1] = Bs[kb + 4 + t][n0 + g];
            }
#pragma unroll
            for (int mi = 0; mi < 4; mi++)
#pragma unroll
                for (int nj = 0; nj < 4; nj++)
                    mma_tf32(acc[mi][nj], a[mi], b[nj]);
        }
        __syncthreads();
    }

    // ---- epilogue
#pragma unroll
    for (int mi = 0; mi < 4; mi++) {
#pragma unroll
        for (int nj = 0; nj < 4; nj++) {
            const int row = by * 128 + wm + mi * 16 + g;
            const int col = bx * 128 + wn + nj * 8 + t * 2;
#pragma unroll
            for (int half = 0; half < 2; half++) {
                const int r = row + half * 8;
                float v0 = acc[mi][nj][half * 2 + 0] + bias[col];
                float v1 = acc[mi][nj][half * 2 + 1] + bias[col + 1];
                if (EPI == 1) {
                    v0 = 0.5f * v0 * (1.0f + erff(v0 * 0.70710678118654752f));
                    v1 = 0.5f * v1 * (1.0f + erff(v1 * 0.70710678118654752f));
                } else if (EPI == 2) {
                    v0 += res[(size_t)r * N + col];
                    v1 += res[(size_t)r * N + col + 1];
                }
                float2 out = make_float2(v0, v1);
                *(float2*)(C + (size_t)r * N + col) = out;
            }
        }
    }
}

// ---------------------------------------------------------------------------
// Attention: one block per (q row, head, batch). 128 threads.
// ---------------------------------------------------------------------------
__global__ void __launch_bounds__(128)
attn_kernel(const float* __restrict__ Q, const float* __restrict__ Kp,
            const float* __restrict__ V, float* __restrict__ O)
{
    __shared__ float q_s[DK];
    __shared__ float sc[S];
    __shared__ float Ks[128][DK + 1];
    __shared__ float red[128];
    __shared__ float part[2][DK];

    const int tid = threadIdx.x;
    const int qi  = blockIdx.x;
    const int hh  = blockIdx.y;
    const int b   = blockIdx.z;

    const float* qrow  = Q  + (size_t)(b * S + qi) * D + hh * DK;
    const float* Kbase = Kp + (size_t)b * S * D + hh * DK;
    const float* Vbase = V  + (size_t)b * S * D + hh * DK;

    if (tid < DK) q_s[tid] = qrow[tid] * 0.125f;
    __syncthreads();

    for (int c0 = 0; c0 < S; c0 += 128) {
        for (int idx = tid; idx < 128 * DK; idx += 128) {
            const int r = idx >> 6, d = idx & 63;
            Ks[r][d] = Kbase[(size_t)(c0 + r) * D + d];
        }
        __syncthreads();
        float s = 0.f;
#pragma unroll
        for (int d = 0; d < DK; d++) s += q_s[d] * Ks[tid][d];
        sc[c0 + tid] = s;
        __syncthreads();
    }

    float m = -1e30f;
    for (int i = tid; i < S; i += 128) m = fmaxf(m, sc[i]);
    red[tid] = m; __syncthreads();
    for (int st = 64; st > 0; st >>= 1) {
        if (tid < st) red[tid] = fmaxf(red[tid], red[tid + st]);
        __syncthreads();
    }
    const float mx = red[0];
    __syncthreads();

    float sum = 0.f;
    for (int i = tid; i < S; i += 128) {
        float e = __expf(sc[i] - mx);
        sc[i] = e;
        sum += e;
    }
    red[tid] = sum; __syncthreads();
    for (int st = 64; st > 0; st >>= 1) {
        if (tid < st) red[tid] += red[tid + st];
        __syncthreads();
    }
    const float inv = 1.0f / red[0];
    __syncthreads();

    const int d = tid & 63;
    const int half = tid >> 6;
    float acc = 0.f;
    const float* vp = Vbase + (size_t)(half * 512) * D + d;
    const float* sp = sc + half * 512;
    for (int k = 0; k < 512; k++) acc += sp[k] * vp[(size_t)k * D];
    part[half][d] = acc;
    __syncthreads();

    if (tid < DK)
        O[(size_t)(b * S + qi) * D + hh * DK + tid] =
            (part[0][tid] + part[1][tid]) * inv;
}

// ---------------------------------------------------------------------------
// LayerNorm over (S,D) per batch
// ---------------------------------------------------------------------------
__global__ void __launch_bounds__(256)
ln_partial(const float* __restrict__ a, const float* __restrict__ c,
           float* __restrict__ y, float* __restrict__ part)
{
    const int b = blockIdx.y, chunk = blockIdx.x, tid = threadIdx.x;
    const size_t base = (size_t)b * S * D + (size_t)chunk * 4096 + tid * 16;
    float s = 0.f, s2 = 0.f;
#pragma unroll
    for (int i = 0; i < 16; i += 4) {
        float4 va = *(const float4*)(a + base + i);
        if (c) {
            float4 vc = *(const float4*)(c + base + i);
            va.x += vc.x; va.y += vc.y; va.z += vc.z; va.w += vc.w;
        }
        if (y) *(float4*)(y + base + i) = va;
        s  += va.x + va.y + va.z + va.w;
        s2 += va.x * va.x + va.y * va.y + va.z * va.z + va.w * va.w;
    }
    __shared__ float r1[256], r2[256];
    r1[tid] = s; r2[tid] = s2; __syncthreads();
    for (int st = 128; st > 0; st >>= 1) {
        if (tid < st) { r1[tid] += r1[tid + st]; r2[tid] += r2[tid + st]; }
        __syncthreads();
    }
    if (tid == 0) {
        part[b * 256 + chunk]            = r1[0];
        part[B * 256 + b * 256 + chunk]  = r2[0];
    }
}

__global__ void __launch_bounds__(256)
ln_finalize(const float* __restrict__ part, float* __restrict__ stats)
{
    const int b = blockIdx.x, tid = threadIdx.x;
    __shared__ float r1[256], r2[256];
    r1[tid] = part[b * 256 + tid];
    r2[tid] = part[B * 256 + b * 256 + tid];
    __syncthreads();
    for (int st = 128; st > 0; st >>= 1) {
        if (tid < st) { r1[tid] += r1[tid + st]; r2[tid] += r2[tid + st]; }
        __syncthreads();
    }
    if (tid == 0) {
        const float n = (float)S * (float)D;
        float mean = r1[0] / n;
        float var  = r2[0] / n - mean * mean;
        stats[2 * b]     = mean;
        stats[2 * b + 1] = rsqrtf(var + EPS);
    }
}

__global__ void __launch_bounds__(256)
ln_apply(const float* __restrict__ y, const float* __restrict__ g,
         const float* __restrict__ beta, const float* __restrict__ stats,
         float* __restrict__ out)
{
    const int b = blockIdx.y;
    const int idx = (blockIdx.x * 256 + threadIdx.x) * 4;
    const float mean = stats[2 * b];
    const float rstd = stats[2 * b + 1];
    const size_t off = (size_t)b * S * D + idx;
    float4 v  = *(const float4*)(y + off);
    float4 gg = *(const float4*)(g + idx);
    float4 bb = *(const float4*)(beta + idx);
    v.x = (v.x - mean) * rstd * gg.x + bb.x;
    v.y = (v.y - mean) * rstd * gg.y + bb.y;
    v.z = (v.z - mean) * rstd * gg.z + bb.z;
    v.w = (v.w - mean) * rstd * gg.w + bb.w;
    *(float4*)(out + off) = v;
}

// ---------------------------------------------------------------------------
// kernel_launch
// ---------------------------------------------------------------------------
extern "C" void kernel_launch(void* const* d_in, const int* in_sizes, int n_in,
                              void* d_out, int out_size)
{
    const float* x    = (const float*)d_in[0];
    const float* wq   = (const float*)d_in[1];
    const float* bq   = (const float*)d_in[2];
    const float* wk   = (const float*)d_in[3];
    const float* bk   = (const float*)d_in[4];
    const float* wv   = (const float*)d_in[5];
    const float* bv   = (const float*)d_in[6];
    const float* ln1g = (const float*)d_in[7];
    const float* ln1b = (const float*)d_in[8];
    const float* w1   = (const float*)d_in[9];
    const float* b1   = (const float*)d_in[10];
    const float* w2   = (const float*)d_in[11];
    const float* b2   = (const float*)d_in[12];
    const float* ln2g = (const float*)d_in[13];
    const float* ln2b = (const float*)d_in[14];
    float* out = (float*)d_out;

    float *q, *k, *v, *ctx, *h, *ff, *part, *stats;
    cudaGetSymbolAddress((void**)&q,     g_q);
    cudaGetSymbolAddress((void**)&k,     g_k);
    cudaGetSymbolAddress((void**)&v,     g_v);
    cudaGetSymbolAddress((void**)&ctx,   g_ctx);
    cudaGetSymbolAddress((void**)&h,     g_h);
    cudaGetSymbolAddress((void**)&ff,    g_ff);
    cudaGetSymbolAddress((void**)&part,  g_part);
    cudaGetSymbolAddress((void**)&stats, g_stats);

    const dim3 gD(D / 128, NT / 128);          // 8 x 64
    const dim3 gF(DFF / 128, NT / 128);        // 32 x 64

    // QKV projections (tf32 tensor cores)
    gemm_tf32<0><<<gD, 256>>>(x, wq, bq, nullptr, q, NT, D, D);
    gemm_tf32<0><<<gD, 256>>>(x, wk, bk, nullptr, k, NT, D, D);
    gemm_tf32<0><<<gD, 256>>>(x, wv, bv, nullptr, v, NT, D, D);

    // Attention
    attn_kernel<<<dim3(S, H, B), 128>>>(q, k, v, ctx);

    // LayerNorm 1: h = LN(x + ctx)
    ln_partial<<<dim3(256, B), 256>>>(x, ctx, h, part);
    ln_finalize<<<B, 256>>>(part, stats);
    ln_apply<<<dim3(1024, B), 256>>>(h, ln1g, ln1b, stats, h);

    // FFN
    gemm_tf32<1><<<gF, 256>>>(h, w1, b1, nullptr, ff, NT, D, DFF);
    gemm_tf32<2><<<gD, 256>>>(ff, w2, b2, h, ctx, NT, DFF, D);

    // LayerNorm 2 -> output
    ln_partial<<<dim3(256, B), 256>>>(ctx, nullptr, nullptr, part);
    ln_finalize<<<B, 256>>>(part, stats);
    ln_apply<<<dim3(1024, B), 256>>>(ctx, ln2g, ln2b, stats, out);
}

// round 4
// speedup vs baseline: 7.4587x; 6.1662x over previous
#include <cuda_runtime.h>
#include <math.h>
#include <stdint.h>

// Problem constants
constexpr int B   = 8;
constexpr int S   = 1024;
constexpr int D   = 1024;
constexpr int H   = 16;
constexpr int DK  = 64;
constexpr int DFF = 4096;
constexpr int NT  = B * S;          // 8192 rows
constexpr float EPS = 1e-5f;

// ---------------------------------------------------------------------------
// Scratch (static __device__ arrays — no runtime allocation)
// ---------------------------------------------------------------------------
__device__ float g_q  [NT * D];
__device__ float g_k  [NT * D];
__device__ float g_v  [NT * D];
__device__ float g_ctx[NT * D];
__device__ float g_h  [NT * D];
__device__ float g_ff [(size_t)NT * DFF];
__device__ float g_part[2 * B * 256];
__device__ float g_stats[2 * B];

// ---------------------------------------------------------------------------
// tf32 helpers
// ---------------------------------------------------------------------------
__device__ __forceinline__ uint32_t f2tf32(float x) {
    uint32_t r;
    asm("cvt.rna.tf32.f32 %0, %1;" : "=r"(r) : "f"(x));
    return r;
}

__device__ __forceinline__ void mma_tf32(float c[4], const uint32_t a[4], const uint32_t b[2]) {
    asm volatile(
        "mma.sync.aligned.m16n8k8.row.col.f32.tf32.tf32.f32 "
        "{%0,%1,%2,%3}, {%4,%5,%6,%7}, {%8,%9}, {%0,%1,%2,%3};\n"
        : "+f"(c[0]), "+f"(c[1]), "+f"(c[2]), "+f"(c[3])
        : "r"(a[0]), "r"(a[1]), "r"(a[2]), "r"(a[3]), "r"(b[0]), "r"(b[1]));
}

// ---------------------------------------------------------------------------
// TF32 tensor-core GEMM: C[M,N] = A[M,K] * W[K,N] + bias[N] (+ epilogue)
// EPI: 0 = bias only, 1 = bias + exact GeLU, 2 = bias + residual add
// ---------------------------------------------------------------------------
template <int EPI>
__global__ void __launch_bounds__(256)
gemm_tf32(const float* __restrict__ A, const float* __restrict__ W,
          const float* __restrict__ bias, const float* __restrict__ res,
          float* __restrict__ C, int M, int K, int N)
{
    __shared__ uint32_t As[128][20];
    __shared__ uint32_t Bs[16][136];

    const int tid  = threadIdx.x;
    const int lane = tid & 31;
    const int warp = tid >> 5;
    const int g    = lane >> 2;
    const int t    = lane & 3;
    const int wm   = (warp & 1) * 64;
    const int wn   = (warp >> 1) * 32;

    const int bx = blockIdx.x;
    const int by = blockIdx.y;

    float acc[4][4][4];
#pragma unroll
    for (int mi = 0; mi < 4; mi++)
#pragma unroll
        for (int nj = 0; nj < 4; nj++)
#pragma unroll
            for (int c = 0; c < 4; c++) acc[mi][nj][c] = 0.f;

    const float* Ab = A + (size_t)(by * 128) * K;
    const float* Wb = W + bx * 128;

    for (int k0 = 0; k0 < K; k0 += 16) {
#pragma unroll
        for (int u = 0; u < 2; u++) {
            const int i   = tid + u * 256;
            const int row = i >> 2;
            const int kq  = (i & 3) * 4;
            float4 v = *(const float4*)(Ab + (size_t)row * K + k0 + kq);
            uint4 w;
            w.x = f2tf32(v.x); w.y = f2tf32(v.y);
            w.z = f2tf32(v.z); w.w = f2tf32(v.w);
            *(uint4*)&As[row][kq] = w;
        }
#pragma unroll
        for (int u = 0; u < 2; u++) {
            const int i   = tid + u * 256;
            const int row = i >> 5;
            const int c4  = (i & 31) * 4;
            float4 v = *(const float4*)(Wb + (size_t)(k0 + row) * N + c4);
            uint4 w;
            w.x = f2tf32(v.x); w.y = f2tf32(v.y);
            w.z = f2tf32(v.z); w.w = f2tf32(v.w);
            *(uint4*)&Bs[row][c4] = w;
        }
        __syncthreads();

#pragma unroll
        for (int ks = 0; ks < 2; ks++) {
            const int kb = ks * 8;
            uint32_t a[4][4], b[4][2];
#pragma unroll
            for (int mi = 0; mi < 4; mi++) {
                const int m0 = wm + mi * 16;
                a[mi][0] = As[m0 + g    ][kb + t    ];
                a[mi][1] = As[m0 + 8 + g][kb + t    ];
                a[mi][2] = As[m0 + g    ][kb + 4 + t];
                a[mi][3] = As[m0 + 8 + g][kb + 4 + t];
            }
#pragma unroll
            for (int nj = 0; nj < 4; nj++) {
                const int n0 = wn + nj * 8;
                b[nj][0] = Bs[kb + t    ][n0 + g];
                b[nj][1] = Bs[kb + 4 + t][n0 + g];
            }
#pragma unroll
            for (int mi = 0; mi < 4; mi++)
#pragma unroll
                for (int nj = 0; nj < 4; nj++)
                    mma_tf32(acc[mi][nj], a[mi], b[nj]);
        }
        __syncthreads();
    }

#pragma unroll
    for (int mi = 0; mi < 4; mi++) {
#pragma unroll
        for (int nj = 0; nj < 4; nj++) {
            const int row = by * 128 + wm + mi * 16 + g;
            const int col = bx * 128 + wn + nj * 8 + t * 2;
#pragma unroll
            for (int half = 0; half < 2; half++) {
                const int r = row + half * 8;
                float v0 = acc[mi][nj][half * 2 + 0] + bias[col];
                float v1 = acc[mi][nj][half * 2 + 1] + bias[col + 1];
                if (EPI == 1) {
                    v0 = 0.5f * v0 * (1.0f + erff(v0 * 0.70710678118654752f));
                    v1 = 0.5f * v1 * (1.0f + erff(v1 * 0.70710678118654752f));
                } else if (EPI == 2) {
                    v0 += res[(size_t)r * N + col];
                    v1 += res[(size_t)r * N + col + 1];
                }
                float2 out = make_float2(v0, v1);
                *(float2*)(C + (size_t)r * N + col) = out;
            }
        }
    }
}

// ---------------------------------------------------------------------------
// Flash attention: one block per (b, h, 128-row q tile). 256 threads, 8 warps.
// Each warp owns 16 q rows. K-tile = 128 keys. Online softmax, tf32 MMA.
// smem strides: P/Q 132 (=4 mod 32), K 68 (=4 mod 32), V 72 (=8 mod 32)
// ---------------------------------------------------------------------------
constexpr int PS_STRIDE = 132;
constexpr int KS_STRIDE = 68;
constexpr int VS_STRIDE = 72;
constexpr int ATTN_SMEM = (128 * PS_STRIDE + 128 * KS_STRIDE + 128 * VS_STRIDE) * 4;

__global__ void __launch_bounds__(256)
flash_attn(const float* __restrict__ Q, const float* __restrict__ Kg,
           const float* __restrict__ Vg, float* __restrict__ O)
{
    extern __shared__ uint32_t smem[];
    uint32_t* Ps = smem;                       // [128][132] (also Q staging)
    uint32_t* Ks = Ps + 128 * PS_STRIDE;       // [128][68]
    uint32_t* Vs = Ks + 128 * KS_STRIDE;       // [128][72]

    const int tid  = threadIdx.x;
    const int lane = tid & 31;
    const int warp = tid >> 5;
    const int g    = lane >> 2;
    const int t    = lane & 3;
    const int m0   = warp * 16;

    const int q0 = blockIdx.x * 128;
    const int h  = blockIdx.y;
    const int b  = blockIdx.z;

    const float* Qb = Q  + (size_t)b * S * D + h * DK;
    const float* Kb = Kg + (size_t)b * S * D + h * DK;
    const float* Vb = Vg + (size_t)b * S * D + h * DK;

    // ---- stage Q tile (scaled by 1/sqrt(DK)) into Ps
#pragma unroll
    for (int u = 0; u < 8; u++) {
        const int idx = u * 256 + tid;
        const int row = idx >> 4;
        const int c4  = (idx & 15) * 4;
        float4 v = *(const float4*)(Qb + (size_t)(q0 + row) * D + c4);
        Ps[row * PS_STRIDE + c4 + 0] = f2tf32(v.x * 0.125f);
        Ps[row * PS_STRIDE + c4 + 1] = f2tf32(v.y * 0.125f);
        Ps[row * PS_STRIDE + c4 + 2] = f2tf32(v.z * 0.125f);
        Ps[row * PS_STRIDE + c4 + 3] = f2tf32(v.w * 0.125f);
    }
    __syncthreads();

    // ---- Q fragments to registers (8 k-chunks over DK=64)
    uint32_t qf[8][4];
#pragma unroll
    for (int kc = 0; kc < 8; kc++) {
        const int kb = kc * 8;
        qf[kc][0] = Ps[(m0 + g)     * PS_STRIDE + kb + t];
        qf[kc][1] = Ps[(m0 + 8 + g) * PS_STRIDE + kb + t];
        qf[kc][2] = Ps[(m0 + g)     * PS_STRIDE + kb + 4 + t];
        qf[kc][3] = Ps[(m0 + 8 + g) * PS_STRIDE + kb + 4 + t];
    }

    float o[8][4];
#pragma unroll
    for (int j = 0; j < 8; j++)
#pragma unroll
        for (int c = 0; c < 4; c++) o[j][c] = 0.f;
    float mrun0 = -1e30f, mrun1 = -1e30f, lrun0 = 0.f, lrun1 = 0.f;

    for (int k0 = 0; k0 < S; k0 += 128) {
        __syncthreads();   // all reads of Ks/Vs from prev iter done
        // ---- stage K, V tiles (128 keys x 64 dk)
#pragma unroll
        for (int u = 0; u < 8; u++) {
            const int idx = u * 256 + tid;
            const int row = idx >> 4;
            const int c4  = (idx & 15) * 4;
            float4 kv = *(const float4*)(Kb + (size_t)(k0 + row) * D + c4);
            Ks[row * KS_STRIDE + c4 + 0] = f2tf32(kv.x);
            Ks[row * KS_STRIDE + c4 + 1] = f2tf32(kv.y);
            Ks[row * KS_STRIDE + c4 + 2] = f2tf32(kv.z);
            Ks[row * KS_STRIDE + c4 + 3] = f2tf32(kv.w);
            float4 vv = *(const float4*)(Vb + (size_t)(k0 + row) * D + c4);
            Vs[row * VS_STRIDE + c4 + 0] = f2tf32(vv.x);
            Vs[row * VS_STRIDE + c4 + 1] = f2tf32(vv.y);
            Vs[row * VS_STRIDE + c4 + 2] = f2tf32(vv.z);
            Vs[row * VS_STRIDE + c4 + 3] = f2tf32(vv.w);
        }
        __syncthreads();

        // ---- S = Q K^T : 16 n-frags (128 keys), 8 k-chunks
        float sc[16][4];
#pragma unroll
        for (int j = 0; j < 16; j++) {
            sc[j][0] = 0.f; sc[j][1] = 0.f; sc[j][2] = 0.f; sc[j][3] = 0.f;
            const int n0 = j * 8;
#pragma unroll
            for (int kc = 0; kc < 8; kc++) {
                const int kb = kc * 8;
                uint32_t bf[2];
                bf[0] = Ks[(n0 + g) * KS_STRIDE + kb + t];
                bf[1] = Ks[(n0 + g) * KS_STRIDE + kb + 4 + t];
                mma_tf32(sc[j], qf[kc], bf);
            }
        }

        // ---- online softmax (rows g and g+8 of warp band)
        float nm0 = -1e30f, nm1 = -1e30f;
#pragma unroll
        for (int j = 0; j < 16; j++) {
            nm0 = fmaxf(nm0, fmaxf(sc[j][0], sc[j][1]));
            nm1 = fmaxf(nm1, fmaxf(sc[j][2], sc[j][3]));
        }
        nm0 = fmaxf(nm0, __shfl_xor_sync(0xffffffffu, nm0, 1));
        nm0 = fmaxf(nm0, __shfl_xor_sync(0xffffffffu, nm0, 2));
        nm1 = fmaxf(nm1, __shfl_xor_sync(0xffffffffu, nm1, 1));
        nm1 = fmaxf(nm1, __shfl_xor_sync(0xffffffffu, nm1, 2));
        const float newm0 = fmaxf(mrun0, nm0);
        const float newm1 = fmaxf(mrun1, nm1);
        const float f0 = __expf(mrun0 - newm0);
        const float f1 = __expf(mrun1 - newm1);

        float s0 = 0.f, s1 = 0.f;
#pragma unroll
        for (int j = 0; j < 16; j++) {
            const float p00 = __expf(sc[j][0] - newm0);
            const float p01 = __expf(sc[j][1] - newm0);
            const float p10 = __expf(sc[j][2] - newm1);
            const float p11 = __expf(sc[j][3] - newm1);
            s0 += p00 + p01;
            s1 += p10 + p11;
            uint2 w0 = make_uint2(f2tf32(p00), f2tf32(p01));
            uint2 w1 = make_uint2(f2tf32(p10), f2tf32(p11));
            *(uint2*)&Ps[(m0 + g)     * PS_STRIDE + j * 8 + 2 * t] = w0;
            *(uint2*)&Ps[(m0 + 8 + g) * PS_STRIDE + j * 8 + 2 * t] = w1;
        }
        s0 += __shfl_xor_sync(0xffffffffu, s0, 1);
        s0 += __shfl_xor_sync(0xffffffffu, s0, 2);
        s1 += __shfl_xor_sync(0xffffffffu, s1, 1);
        s1 += __shfl_xor_sync(0xffffffffu, s1, 2);
        lrun0 = lrun0 * f0 + s0;
        lrun1 = lrun1 * f1 + s1;
        mrun0 = newm0;
        mrun1 = newm1;
#pragma unroll
        for (int j = 0; j < 8; j++) {
            o[j][0] *= f0; o[j][1] *= f0;
            o[j][2] *= f1; o[j][3] *= f1;
        }
        __syncwarp();   // P writes visible within warp before A-frag reads

        // ---- O += P V : 16 k-chunks (128 keys), 8 n-frags (64 dk)
#pragma unroll
        for (int kc = 0; kc < 16; kc++) {
            const int kb = kc * 8;
            uint32_t a[4];
            a[0] = Ps[(m0 + g)     * PS_STRIDE + kb + t];
            a[1] = Ps[(m0 + 8 + g) * PS_STRIDE + kb + t];
            a[2] = Ps[(m0 + g)     * PS_STRIDE + kb + 4 + t];
            a[3] = Ps[(m0 + 8 + g) * PS_STRIDE + kb + 4 + t];
#pragma unroll
            for (int j = 0; j < 8; j++) {
                uint32_t bf[2];
                bf[0] = Vs[(kb + t)     * VS_STRIDE + j * 8 + g];
                bf[1] = Vs[(kb + 4 + t) * VS_STRIDE + j * 8 + g];
                mma_tf32(o[j], a, bf);
            }
        }
    }

    // ---- epilogue: normalize and store
    const float inv0 = 1.0f / lrun0;
    const float inv1 = 1.0f / lrun1;
    const int row0 = q0 + m0 + g;
    const int row1 = row0 + 8;
#pragma unroll
    for (int j = 0; j < 8; j++) {
        const int col = h * DK + j * 8 + 2 * t;
        float2 r0 = make_float2(o[j][0] * inv0, o[j][1] * inv0);
        float2 r1 = make_float2(o[j][2] * inv1, o[j][3] * inv1);
        *(float2*)(O + (size_t)(b * S + row0) * D + col) = r0;
        *(float2*)(O + (size_t)(b * S + row1) * D + col) = r1;
    }
}

// ---------------------------------------------------------------------------
// LayerNorm over (S,D) per batch
// ---------------------------------------------------------------------------
__global__ void __launch_bounds__(256)
ln_partial(const float* __restrict__ a, const float* __restrict__ c,
           float* __restrict__ y, float* __restrict__ part)
{
    const int b = blockIdx.y, chunk = blockIdx.x, tid = threadIdx.x;
    const size_t base = (size_t)b * S * D + (size_t)chunk * 4096 + tid * 16;
    float s = 0.f, s2 = 0.f;
#pragma unroll
    for (int i = 0; i < 16; i += 4) {
        float4 va = *(const float4*)(a + base + i);
        if (c) {
            float4 vc = *(const float4*)(c + base + i);
            va.x += vc.x; va.y += vc.y; va.z += vc.z; va.w += vc.w;
        }
        if (y) *(float4*)(y + base + i) = va;
        s  += va.x + va.y + va.z + va.w;
        s2 += va.x * va.x + va.y * va.y + va.z * va.z + va.w * va.w;
    }
    __shared__ float r1[256], r2[256];
    r1[tid] = s; r2[tid] = s2; __syncthreads();
    for (int st = 128; st > 0; st >>= 1) {
        if (tid < st) { r1[tid] += r1[tid + st]; r2[tid] += r2[tid + st]; }
        __syncthreads();
    }
    if (tid == 0) {
        part[b * 256 + chunk]            = r1[0];
        part[B * 256 + b * 256 + chunk]  = r2[0];
    }
}

__global__ void __launch_bounds__(256)
ln_finalize(const float* __restrict__ part, float* __restrict__ stats)
{
    const int b = blockIdx.x, tid = threadIdx.x;
    __shared__ float r1[256], r2[256];
    r1[tid] = part[b * 256 + tid];
    r2[tid] = part[B * 256 + b * 256 + tid];
    __syncthreads();
    for (int st = 128; st > 0; st >>= 1) {
        if (tid < st) { r1[tid] += r1[tid + st]; r2[tid] += r2[tid + st]; }
        __syncthreads();
    }
    if (tid == 0) {
        const float n = (float)S * (float)D;
        float mean = r1[0] / n;
        float var  = r2[0] / n - mean * mean;
        stats[2 * b]     = mean;
        stats[2 * b + 1] = rsqrtf(var + EPS);
    }
}

__global__ void __launch_bounds__(256)
ln_apply(const float* __restrict__ y, const float* __restrict__ g,
         const float* __restrict__ beta, const float* __restrict__ stats,
         float* __restrict__ out)
{
    const int b = blockIdx.y;
    const int idx = (blockIdx.x * 256 + threadIdx.x) * 4;
    const float mean = stats[2 * b];
    const float rstd = stats[2 * b + 1];
    const size_t off = (size_t)b * S * D + idx;
    float4 v  = *(const float4*)(y + off);
    float4 gg = *(const float4*)(g + idx);
    float4 bb = *(const float4*)(beta + idx);
    v.x = (v.x - mean) * rstd * gg.x + bb.x;
    v.y = (v.y - mean) * rstd * gg.y + bb.y;
    v.z = (v.z - mean) * rstd * gg.z + bb.z;
    v.w = (v.w - mean) * rstd * gg.w + bb.w;
    *(float4*)(out + off) = v;
}

// ---------------------------------------------------------------------------
// kernel_launch
// ---------------------------------------------------------------------------
extern "C" void kernel_launch(void* const* d_in, const int* in_sizes, int n_in,
                              void* d_out, int out_size)
{
    const float* x    = (const float*)d_in[0];
    const float* wq   = (const float*)d_in[1];
    const float* bq   = (const float*)d_in[2];
    const float* wk   = (const float*)d_in[3];
    const float* bk   = (const float*)d_in[4];
    const float* wv   = (const float*)d_in[5];
    const float* bv   = (const float*)d_in[6];
    const float* ln1g = (const float*)d_in[7];
    const float* ln1b = (const float*)d_in[8];
    const float* w1   = (const float*)d_in[9];
    const float* b1   = (const float*)d_in[10];
    const float* w2   = (const float*)d_in[11];
    const float* b2   = (const float*)d_in[12];
    const float* ln2g = (const float*)d_in[13];
    const float* ln2b = (const float*)d_in[14];
    float* out = (float*)d_out;

    float *q, *k, *v, *ctx, *h, *ff, *part, *stats;
    cudaGetSymbolAddress((void**)&q,     g_q);
    cudaGetSymbolAddress((void**)&k,     g_k);
    cudaGetSymbolAddress((void**)&v,     g_v);
    cudaGetSymbolAddress((void**)&ctx,   g_ctx);
    cudaGetSymbolAddress((void**)&h,     g_h);
    cudaGetSymbolAddress((void**)&ff,    g_ff);
    cudaGetSymbolAddress((void**)&part,  g_part);
    cudaGetSymbolAddress((void**)&stats, g_stats);

    cudaFuncSetAttribute(flash_attn,
                         cudaFuncAttributeMaxDynamicSharedMemorySize, ATTN_SMEM);

    const dim3 gD(D / 128, NT / 128);          // 8 x 64
    const dim3 gF(DFF / 128, NT / 128);        // 32 x 64

    // QKV projections (tf32 tensor cores)
    gemm_tf32<0><<<gD, 256>>>(x, wq, bq, nullptr, q, NT, D, D);
    gemm_tf32<0><<<gD, 256>>>(x, wk, bk, nullptr, k, NT, D, D);
    gemm_tf32<0><<<gD, 256>>>(x, wv, bv, nullptr, v, NT, D, D);

    // Flash attention
    flash_attn<<<dim3(S / 128, H, B), 256, ATTN_SMEM>>>(q, k, v, ctx);

    // LayerNorm 1: h = LN(x + ctx)
    ln_partial<<<dim3(256, B), 256>>>(x, ctx, h, part);
    ln_finalize<<<B, 256>>>(part, stats);
    ln_apply<<<dim3(1024, B), 256>>>(h, ln1g, ln1b, stats, h);

    // FFN
    gemm_tf32<1><<<gF, 256>>>(h, w1, b1, nullptr, ff, NT, D, DFF);
    gemm_tf32<2><<<gD, 256>>>(ff, w2, b2, h, ctx, NT, DFF, D);

    // LayerNorm 2 -> output
    ln_partial<<<dim3(256, B), 256>>>(ctx, nullptr, nullptr, part);
    ln_finalize<<<B, 256>>>(part, stats);
    ln_apply<<<dim3(1024, B), 256>>>(ctx, ln2g, ln2b, stats, out);
}

// round 5
// speedup vs baseline: 9.0257x; 1.2101x over previous
#include <cuda_runtime.h>
#include <math.h>
#include <stdint.h>

// Problem constants
constexpr int B   = 8;
constexpr int S   = 1024;
constexpr int D   = 1024;
constexpr int H   = 16;
constexpr int DK  = 64;
constexpr int DFF = 4096;
constexpr int NT  = B * S;          // 8192 rows
constexpr float EPS = 1e-5f;

// ---------------------------------------------------------------------------
// Scratch (static __device__ arrays — no runtime allocation)
// ---------------------------------------------------------------------------
__device__ float g_q  [NT * D];
__device__ float g_k  [NT * D];
__device__ float g_v  [NT * D];
__device__ float g_ctx[NT * D];
__device__ float g_h  [NT * D];
__device__ float g_ff [(size_t)NT * DFF];
__device__ float g_part[2 * B * 256];
__device__ float g_stats[2 * B];

// ---------------------------------------------------------------------------
// tf32 / async helpers
// ---------------------------------------------------------------------------
__device__ __forceinline__ uint32_t f2tf32(float x) {
    uint32_t r;
    asm("cvt.rna.tf32.f32 %0, %1;" : "=r"(r) : "f"(x));
    return r;
}

__device__ __forceinline__ void mma_tf32(float c[4], const uint32_t a[4], const uint32_t b[2]) {
    asm volatile(
        "mma.sync.aligned.m16n8k8.row.col.f32.tf32.tf32.f32 "
        "{%0,%1,%2,%3}, {%4,%5,%6,%7}, {%8,%9}, {%0,%1,%2,%3};\n"
        : "+f"(c[0]), "+f"(c[1]), "+f"(c[2]), "+f"(c[3])
        : "r"(a[0]), "r"(a[1]), "r"(a[2]), "r"(a[3]), "r"(b[0]), "r"(b[1]));
}

__device__ __forceinline__ void cp_async16(void* smem_ptr, const void* gptr) {
    uint32_t sa = (uint32_t)__cvta_generic_to_shared(smem_ptr);
    asm volatile("cp.async.cg.shared.global [%0], [%1], 16;\n" :: "r"(sa), "l"(gptr));
}
__device__ __forceinline__ void cp_commit() {
    asm volatile("cp.async.commit_group;\n");
}
template <int N>
__device__ __forceinline__ void cp_wait() {
    asm volatile("cp.async.wait_group %0;\n" :: "n"(N));
}

// ---------------------------------------------------------------------------
// Pipelined TF32 GEMM body: C[.,N] tile (128x128) = A[.,K] * W[K,N] + bias
// BK=32, 3-stage cp.async pipeline, fp32 in smem, cvt at fragment load.
// EPI: 0 = bias only, 1 = bias + exact GeLU, 2 = bias + residual add
// ---------------------------------------------------------------------------
constexpr int ASZ = 128 * 36;    // A stage: [128][36] (stride 36 => banks 4g+t)
constexpr int BSZ = 32 * 136;    // B stage: [32][136] (stride 136 => banks 8t+g)
constexpr int GEMM_SMEM = 3 * (ASZ + BSZ) * 4;   // 107,520 B

template <int EPI>
__device__ __forceinline__ void gemm_body(
    const float* __restrict__ A, const float* __restrict__ W,
    const float* __restrict__ bias, const float* __restrict__ res,
    float* __restrict__ C, int K, int N, int bx, int by, float* sm)
{
    float* AsB = sm;
    float* BsB = sm + 3 * ASZ;

    const int tid  = threadIdx.x;
    const int lane = tid & 31;
    const int warp = tid >> 5;
    const int g    = lane >> 2;
    const int t    = lane & 3;
    const int wm   = (warp & 1) * 64;
    const int wn   = (warp >> 1) * 32;

    const float* Ab = A + (size_t)(by * 128) * K;
    const float* Wb = W + bx * 128;

    float acc[4][4][4];
#pragma unroll
    for (int mi = 0; mi < 4; mi++)
#pragma unroll
        for (int nj = 0; nj < 4; nj++)
#pragma unroll
            for (int c = 0; c < 4; c++) acc[mi][nj][c] = 0.f;

    // stage a BK=32 tile into buffer `buf`
    auto stage = [&](int buf, int kk) {
        float* Ad = AsB + buf * ASZ;
        float* Bd = BsB + buf * BSZ;
#pragma unroll
        for (int u = 0; u < 4; u++) {
            const int i   = tid + u * 256;
            const int row = i >> 3;
            const int c4  = (i & 7) * 4;
            cp_async16(Ad + row * 36 + c4, Ab + (size_t)row * K + kk + c4);
        }
#pragma unroll
        for (int u = 0; u < 4; u++) {
            const int i   = tid + u * 256;
            const int row = i >> 5;
            const int c4  = (i & 31) * 4;
            cp_async16(Bd + row * 136 + c4, Wb + (size_t)(kk + row) * N + c4);
        }
        cp_commit();
    };

    const int nT = K >> 5;
    stage(0, 0);
    if (nT > 1) stage(1, 32);

    for (int tt = 0; tt < nT; tt++) {
        if (tt + 1 < nT) cp_wait<1>(); else cp_wait<0>();
        __syncthreads();
        if (tt + 2 < nT) stage((tt + 2) % 3, (tt + 2) * 32);

        const float* Ac = AsB + (tt % 3) * ASZ;
        const float* Bc = BsB + (tt % 3) * BSZ;
#pragma unroll
        for (int ks = 0; ks < 4; ks++) {
            const int kb = ks * 8;
            uint32_t a[4][4], b[4][2];
#pragma unroll
            for (int mi = 0; mi < 4; mi++) {
                const int m0 = wm + mi * 16;
                a[mi][0] = f2tf32(Ac[(m0 + g)     * 36 + kb + t]);
                a[mi][1] = f2tf32(Ac[(m0 + 8 + g) * 36 + kb + t]);
                a[mi][2] = f2tf32(Ac[(m0 + g)     * 36 + kb + 4 + t]);
                a[mi][3] = f2tf32(Ac[(m0 + 8 + g) * 36 + kb + 4 + t]);
            }
#pragma unroll
            for (int nj = 0; nj < 4; nj++) {
                const int n0 = wn + nj * 8;
                b[nj][0] = f2tf32(Bc[(kb + t)     * 136 + n0 + g]);
                b[nj][1] = f2tf32(Bc[(kb + 4 + t) * 136 + n0 + g]);
            }
#pragma unroll
            for (int mi = 0; mi < 4; mi++)
#pragma unroll
                for (int nj = 0; nj < 4; nj++)
                    mma_tf32(acc[mi][nj], a[mi], b[nj]);
        }
    }

    // epilogue
#pragma unroll
    for (int mi = 0; mi < 4; mi++) {
#pragma unroll
        for (int nj = 0; nj < 4; nj++) {
            const int row = by * 128 + wm + mi * 16 + g;
            const int col = bx * 128 + wn + nj * 8 + t * 2;
#pragma unroll
            for (int half = 0; half < 2; half++) {
                const int r = row + half * 8;
                float v0 = acc[mi][nj][half * 2 + 0] + bias[col];
                float v1 = acc[mi][nj][half * 2 + 1] + bias[col + 1];
                if (EPI == 1) {
                    v0 = 0.5f * v0 * (1.0f + erff(v0 * 0.70710678118654752f));
                    v1 = 0.5f * v1 * (1.0f + erff(v1 * 0.70710678118654752f));
                } else if (EPI == 2) {
                    v0 += res[(size_t)r * N + col];
                    v1 += res[(size_t)r * N + col + 1];
                }
                float2 out = make_float2(v0, v1);
                *(float2*)(C + (size_t)r * N + col) = out;
            }
        }
    }
}

// Fused QKV: blockIdx.z selects {q,k,v}
__global__ void __launch_bounds__(256)
gemm_qkv(const float* __restrict__ x,
         const float* __restrict__ wq, const float* __restrict__ bq,
         const float* __restrict__ wk, const float* __restrict__ bk,
         const float* __restrict__ wv, const float* __restrict__ bv,
         float* __restrict__ q, float* __restrict__ k, float* __restrict__ v)
{
    extern __shared__ float sm[];
    const float* W; const float* bias; float* C;
    if (blockIdx.z == 0)      { W = wq; bias = bq; C = q; }
    else if (blockIdx.z == 1) { W = wk; bias = bk; C = k; }
    else                      { W = wv; bias = bv; C = v; }
    gemm_body<0>(x, W, bias, nullptr, C, D, D, blockIdx.x, blockIdx.y, sm);
}

template <int EPI>
__global__ void __launch_bounds__(256)
gemm_pipe(const float* __restrict__ A, const float* __restrict__ W,
          const float* __restrict__ bias, const float* __restrict__ res,
          float* __restrict__ C, int K, int N)
{
    extern __shared__ float sm[];
    gemm_body<EPI>(A, W, bias, res, C, K, N, blockIdx.x, blockIdx.y, sm);
}

// ---------------------------------------------------------------------------
// Flash attention: one block per (b, h, 128-row q tile). 256 threads, 8 warps.
// ---------------------------------------------------------------------------
constexpr int PS_STRIDE = 132;
constexpr int KS_STRIDE = 68;
constexpr int VS_STRIDE = 72;
constexpr int ATTN_SMEM = (128 * PS_STRIDE + 128 * KS_STRIDE + 128 * VS_STRIDE) * 4;

__global__ void __launch_bounds__(256)
flash_attn(const float* __restrict__ Q, const float* __restrict__ Kg,
           const float* __restrict__ Vg, float* __restrict__ O)
{
    extern __shared__ uint32_t smem[];
    uint32_t* Ps = smem;
    uint32_t* Ks = Ps + 128 * PS_STRIDE;
    uint32_t* Vs = Ks + 128 * KS_STRIDE;

    const int tid  = threadIdx.x;
    const int lane = tid & 31;
    const int warp = tid >> 5;
    const int g    = lane >> 2;
    const int t    = lane & 3;
    const int m0   = warp * 16;

    const int q0 = blockIdx.x * 128;
    const int h  = blockIdx.y;
    const int b  = blockIdx.z;

    const float* Qb = Q  + (size_t)b * S * D + h * DK;
    const float* Kb = Kg + (size_t)b * S * D + h * DK;
    const float* Vb = Vg + (size_t)b * S * D + h * DK;

#pragma unroll
    for (int u = 0; u < 8; u++) {
        const int idx = u * 256 + tid;
        const int row = idx >> 4;
        const int c4  = (idx & 15) * 4;
        float4 v = *(const float4*)(Qb + (size_t)(q0 + row) * D + c4);
        Ps[row * PS_STRIDE + c4 + 0] = f2tf32(v.x * 0.125f);
        Ps[row * PS_STRIDE + c4 + 1] = f2tf32(v.y * 0.125f);
        Ps[row * PS_STRIDE + c4 + 2] = f2tf32(v.z * 0.125f);
        Ps[row * PS_STRIDE + c4 + 3] = f2tf32(v.w * 0.125f);
    }
    __syncthreads();

    uint32_t qf[8][4];
#pragma unroll
    for (int kc = 0; kc < 8; kc++) {
        const int kb = kc * 8;
        qf[kc][0] = Ps[(m0 + g)     * PS_STRIDE + kb + t];
        qf[kc][1] = Ps[(m0 + 8 + g) * PS_STRIDE + kb + t];
        qf[kc][2] = Ps[(m0 + g)     * PS_STRIDE + kb + 4 + t];
        qf[kc][3] = Ps[(m0 + 8 + g) * PS_STRIDE + kb + 4 + t];
    }

    float o[8][4];
#pragma unroll
    for (int j = 0; j < 8; j++)
#pragma unroll
        for (int c = 0; c < 4; c++) o[j][c] = 0.f;
    float mrun0 = -1e30f, mrun1 = -1e30f, lrun0 = 0.f, lrun1 = 0.f;

    for (int k0 = 0; k0 < S; k0 += 128) {
        __syncthreads();
#pragma unroll
        for (int u = 0; u < 8; u++) {
            const int idx = u * 256 + tid;
            const int row = idx >> 4;
            const int c4  = (idx & 15) * 4;
            float4 kv = *(const float4*)(Kb + (size_t)(k0 + row) * D + c4);
            Ks[row * KS_STRIDE + c4 + 0] = f2tf32(kv.x);
            Ks[row * KS_STRIDE + c4 + 1] = f2tf32(kv.y);
            Ks[row * KS_STRIDE + c4 + 2] = f2tf32(kv.z);
            Ks[row * KS_STRIDE + c4 + 3] = f2tf32(kv.w);
            float4 vv = *(const float4*)(Vb + (size_t)(k0 + row) * D + c4);
            Vs[row * VS_STRIDE + c4 + 0] = f2tf32(vv.x);
            Vs[row * VS_STRIDE + c4 + 1] = f2tf32(vv.y);
            Vs[row * VS_STRIDE + c4 + 2] = f2tf32(vv.z);
            Vs[row * VS_STRIDE + c4 + 3] = f2tf32(vv.w);
        }
        __syncthreads();

        float sc[16][4];
#pragma unroll
        for (int j = 0; j < 16; j++) {
            sc[j][0] = 0.f; sc[j][1] = 0.f; sc[j][2] = 0.f; sc[j][3] = 0.f;
            const int n0 = j * 8;
#pragma unroll
            for (int kc = 0; kc < 8; kc++) {
                const int kb = kc * 8;
                uint32_t bf[2];
                bf[0] = Ks[(n0 + g) * KS_STRIDE + kb + t];
                bf[1] = Ks[(n0 + g) * KS_STRIDE + kb + 4 + t];
                mma_tf32(sc[j], qf[kc], bf);
            }
        }

        float nm0 = -1e30f, nm1 = -1e30f;
#pragma unroll
        for (int j = 0; j < 16; j++) {
            nm0 = fmaxf(nm0, fmaxf(sc[j][0], sc[j][1]));
            nm1 = fmaxf(nm1, fmaxf(sc[j][2], sc[j][3]));
        }
        nm0 = fmaxf(nm0, __shfl_xor_sync(0xffffffffu, nm0, 1));
        nm0 = fmaxf(nm0, __shfl_xor_sync(0xffffffffu, nm0, 2));
        nm1 = fmaxf(nm1, __shfl_xor_sync(0xffffffffu, nm1, 1));
        nm1 = fmaxf(nm1, __shfl_xor_sync(0xffffffffu, nm1, 2));
        const float newm0 = fmaxf(mrun0, nm0);
        const float newm1 = fmaxf(mrun1, nm1);
        const float f0 = __expf(mrun0 - newm0);
        const float f1 = __expf(mrun1 - newm1);

        float s0 = 0.f, s1 = 0.f;
#pragma unroll
        for (int j = 0; j < 16; j++) {
            const float p00 = __expf(sc[j][0] - newm0);
            const float p01 = __expf(sc[j][1] - newm0);
            const float p10 = __expf(sc[j][2] - newm1);
            const float p11 = __expf(sc[j][3] - newm1);
            s0 += p00 + p01;
            s1 += p10 + p11;
            uint2 w0 = make_uint2(f2tf32(p00), f2tf32(p01));
            uint2 w1 = make_uint2(f2tf32(p10), f2tf32(p11));
            *(uint2*)&Ps[(m0 + g)     * PS_STRIDE + j * 8 + 2 * t] = w0;
            *(uint2*)&Ps[(m0 + 8 + g) * PS_STRIDE + j * 8 + 2 * t] = w1;
        }
        s0 += __shfl_xor_sync(0xffffffffu, s0, 1);
        s0 += __shfl_xor_sync(0xffffffffu, s0, 2);
        s1 += __shfl_xor_sync(0xffffffffu, s1, 1);
        s1 += __shfl_xor_sync(0xffffffffu, s1, 2);
        lrun0 = lrun0 * f0 + s0;
        lrun1 = lrun1 * f1 + s1;
        mrun0 = newm0;
        mrun1 = newm1;
#pragma unroll
        for (int j = 0; j < 8; j++) {
            o[j][0] *= f0; o[j][1] *= f0;
            o[j][2] *= f1; o[j][3] *= f1;
        }
        __syncwarp();

#pragma unroll
        for (int kc = 0; kc < 16; kc++) {
            const int kb = kc * 8;
            uint32_t a[4];
            a[0] = Ps[(m0 + g)     * PS_STRIDE + kb + t];
            a[1] = Ps[(m0 + 8 + g) * PS_STRIDE + kb + t];
            a[2] = Ps[(m0 + g)     * PS_STRIDE + kb + 4 + t];
            a[3] = Ps[(m0 + 8 + g) * PS_STRIDE + kb + 4 + t];
#pragma unroll
            for (int j = 0; j < 8; j++) {
                uint32_t bf[2];
                bf[0] = Vs[(kb + t)     * VS_STRIDE + j * 8 + g];
                bf[1] = Vs[(kb + 4 + t) * VS_STRIDE + j * 8 + g];
                mma_tf32(o[j], a, bf);
            }
        }
    }

    const float inv0 = 1.0f / lrun0;
    const float inv1 = 1.0f / lrun1;
    const int row0 = q0 + m0 + g;
    const int row1 = row0 + 8;
#pragma unroll
    for (int j = 0; j < 8; j++) {
        const int col = h * DK + j * 8 + 2 * t;
        float2 r0 = make_float2(o[j][0] * inv0, o[j][1] * inv0);
        float2 r1 = make_float2(o[j][2] * inv1, o[j][3] * inv1);
        *(float2*)(O + (size_t)(b * S + row0) * D + col) = r0;
        *(float2*)(O + (size_t)(b * S + row1) * D + col) = r1;
    }
}

// ---------------------------------------------------------------------------
// LayerNorm over (S,D) per batch
// ---------------------------------------------------------------------------
__global__ void __launch_bounds__(256)
ln_partial(const float* __restrict__ a, const float* __restrict__ c,
           float* __restrict__ y, float* __restrict__ part)
{
    const int b = blockIdx.y, chunk = blockIdx.x, tid = threadIdx.x;
    const size_t base = (size_t)b * S * D + (size_t)chunk * 4096 + tid * 16;
    float s = 0.f, s2 = 0.f;
#pragma unroll
    for (int i = 0; i < 16; i += 4) {
        float4 va = *(const float4*)(a + base + i);
        if (c) {
            float4 vc = *(const float4*)(c + base + i);
            va.x += vc.x; va.y += vc.y; va.z += vc.z; va.w += vc.w;
        }
        if (y) *(float4*)(y + base + i) = va;
        s  += va.x + va.y + va.z + va.w;
        s2 += va.x * va.x + va.y * va.y + va.z * va.z + va.w * va.w;
    }
    __shared__ float r1[256], r2[256];
    r1[tid] = s; r2[tid] = s2; __syncthreads();
    for (int st = 128; st > 0; st >>= 1) {
        if (tid < st) { r1[tid] += r1[tid + st]; r2[tid] += r2[tid + st]; }
        __syncthreads();
    }
    if (tid == 0) {
        part[b * 256 + chunk]            = r1[0];
        part[B * 256 + b * 256 + chunk]  = r2[0];
    }
}

__global__ void __launch_bounds__(256)
ln_finalize(const float* __restrict__ part, float* __restrict__ stats)
{
    const int b = blockIdx.x, tid = threadIdx.x;
    __shared__ float r1[256], r2[256];
    r1[tid] = part[b * 256 + tid];
    r2[tid] = part[B * 256 + b * 256 + tid];
    __syncthreads();
    for (int st = 128; st > 0; st >>= 1) {
        if (tid < st) { r1[tid] += r1[tid + st]; r2[tid] += r2[tid + st]; }
        __syncthreads();
    }
    if (tid == 0) {
        const float n = (float)S * (float)D;
        float mean = r1[0] / n;
        float var  = r2[0] / n - mean * mean;
        stats[2 * b]     = mean;
        stats[2 * b + 1] = rsqrtf(var + EPS);
    }
}

__global__ void __launch_bounds__(256)
ln_apply(const float* __restrict__ y, const float* __restrict__ g,
         const float* __restrict__ beta, const float* __restrict__ stats,
         float* __restrict__ out)
{
    const int b = blockIdx.y;
    const int idx = (blockIdx.x * 256 + threadIdx.x) * 4;
    const float mean = stats[2 * b];
    const float rstd = stats[2 * b + 1];
    const size_t off = (size_t)b * S * D + idx;
    float4 v  = *(const float4*)(y + off);
    float4 gg = *(const float4*)(g + idx);
    float4 bb = *(const float4*)(beta + idx);
    v.x = (v.x - mean) * rstd * gg.x + bb.x;
    v.y = (v.y - mean) * rstd * gg.y + bb.y;
    v.z = (v.z - mean) * rstd * gg.z + bb.z;
    v.w = (v.w - mean) * rstd * gg.w + bb.w;
    *(float4*)(out + off) = v;
}

// ---------------------------------------------------------------------------
// kernel_launch
// ---------------------------------------------------------------------------
extern "C" void kernel_launch(void* const* d_in, const int* in_sizes, int n_in,
                              void* d_out, int out_size)
{
    const float* x    = (const float*)d_in[0];
    const float* wq   = (const float*)d_in[1];
    const float* bq   = (const float*)d_in[2];
    const float* wk   = (const float*)d_in[3];
    const float* bk   = (const float*)d_in[4];
    const float* wv   = (const float*)d_in[5];
    const float* bv   = (const float*)d_in[6];
    const float* ln1g = (const float*)d_in[7];
    const float* ln1b = (const float*)d_in[8];
    const float* w1   = (const float*)d_in[9];
    const float* b1   = (const float*)d_in[10];
    const float* w2   = (const float*)d_in[11];
    const float* b2   = (const float*)d_in[12];
    const float* ln2g = (const float*)d_in[13];
    const float* ln2b = (const float*)d_in[14];
    float* out = (float*)d_out;

    float *q, *k, *v, *ctx, *h, *ff, *part, *stats;
    cudaGetSymbolAddress((void**)&q,     g_q);
    cudaGetSymbolAddress((void**)&k,     g_k);
    cudaGetSymbolAddress((void**)&v,     g_v);
    cudaGetSymbolAddress((void**)&ctx,   g_ctx);
    cudaGetSymbolAddress((void**)&h,     g_h);
    cudaGetSymbolAddress((void**)&ff,    g_ff);
    cudaGetSymbolAddress((void**)&part,  g_part);
    cudaGetSymbolAddress((void**)&stats, g_stats);

    static bool attr_done = false;
    if (!attr_done) {
        cudaFuncSetAttribute(flash_attn,
                             cudaFuncAttributeMaxDynamicSharedMemorySize, ATTN_SMEM);
        cudaFuncSetAttribute(gemm_qkv,
                             cudaFuncAttributeMaxDynamicSharedMemorySize, GEMM_SMEM);
        cudaFuncSetAttribute(gemm_pipe<1>,
                             cudaFuncAttributeMaxDynamicSharedMemorySize, GEMM_SMEM);
        cudaFuncSetAttribute(gemm_pipe<2>,
                             cudaFuncAttributeMaxDynamicSharedMemorySize, GEMM_SMEM);
        attr_done = true;
    }

    // QKV projections (fused launch, tf32 tensor cores, cp.async pipeline)
    gemm_qkv<<<dim3(D / 128, NT / 128, 3), 256, GEMM_SMEM>>>(
        x, wq, bq, wk, bk, wv, bv, q, k, v);

    // Flash attention
    flash_attn<<<dim3(S / 128, H, B), 256, ATTN_SMEM>>>(q, k, v, ctx);

    // LayerNorm 1: h = LN(x + ctx)
    ln_partial<<<dim3(256, B), 256>>>(x, ctx, h, part);
    ln_finalize<<<B, 256>>>(part, stats);
    ln_apply<<<dim3(1024, B), 256>>>(h, ln1g, ln1b, stats, h);

    // FFN
    gemm_pipe<1><<<dim3(DFF / 128, NT / 128), 256, GEMM_SMEM>>>(h, w1, b1, nullptr, ff, D, DFF);
    gemm_pipe<2><<<dim3(D / 128, NT / 128), 256, GEMM_SMEM>>>(ff, w2, b2, h, ctx, DFF, D);

    // LayerNorm 2 -> output
    ln_partial<<<dim3(256, B), 256>>>(ctx, nullptr, nullptr, part);
    ln_finalize<<<B, 256>>>(part, stats);
    ln_apply<<<dim3(1024, B), 256>>>(ctx, ln2g, ln2b, stats, out);
}

// round 6
// speedup vs baseline: 9.6970x; 1.0744x over previous
#include <cuda_runtime.h>
#include <math.h>
#include <stdint.h>

// Problem constants
constexpr int B   = 8;
constexpr int S   = 1024;
constexpr int D   = 1024;
constexpr int H   = 16;
constexpr int DK  = 64;
constexpr int DFF = 4096;
constexpr int NT  = B * S;          // 8192 rows
constexpr float EPS = 1e-5f;

// ---------------------------------------------------------------------------
// Scratch (static __device__ arrays — no runtime allocation)
// ---------------------------------------------------------------------------
__device__ float g_q  [NT * D];
__device__ float g_k  [NT * D];
__device__ float g_v  [NT * D];
__device__ float g_ctx[NT * D];
__device__ float g_h  [NT * D];
__device__ float g_ff [(size_t)NT * DFF];
__device__ float g_part[2 * B * 256];
__device__ float g_stats[2 * B];
// tf32-pre-rounded operand copies
__device__ float g_xr [NT * D];
__device__ float g_hr [NT * D];
__device__ float g_wqr[D * D];
__device__ float g_wkr[D * D];
__device__ float g_wvr[D * D];
__device__ float g_w1r[D * DFF];
__device__ float g_w2r[DFF * D];

// ---------------------------------------------------------------------------
// tf32 / async helpers
// ---------------------------------------------------------------------------
__device__ __forceinline__ uint32_t f2tf32(float x) {
    uint32_t r;
    asm("cvt.rna.tf32.f32 %0, %1;" : "=r"(r) : "f"(x));
    return r;
}

__device__ __forceinline__ void mma_tf32(float c[4], const uint32_t a[4], const uint32_t b[2]) {
    asm volatile(
        "mma.sync.aligned.m16n8k8.row.col.f32.tf32.tf32.f32 "
        "{%0,%1,%2,%3}, {%4,%5,%6,%7}, {%8,%9}, {%0,%1,%2,%3};\n"
        : "+f"(c[0]), "+f"(c[1]), "+f"(c[2]), "+f"(c[3])
        : "r"(a[0]), "r"(a[1]), "r"(a[2]), "r"(a[3]), "r"(b[0]), "r"(b[1]));
}

__device__ __forceinline__ void cp_async16(void* smem_ptr, const void* gptr) {
    uint32_t sa = (uint32_t)__cvta_generic_to_shared(smem_ptr);
    asm volatile("cp.async.cg.shared.global [%0], [%1], 16;\n" :: "r"(sa), "l"(gptr));
}
__device__ __forceinline__ void cp_commit() {
    asm volatile("cp.async.commit_group;\n");
}
template <int N>
__device__ __forceinline__ void cp_wait() {
    asm volatile("cp.async.wait_group %0;\n" :: "n"(N));
}

// ---------------------------------------------------------------------------
// Elementwise tf32 rounding pre-pass (float4)
// ---------------------------------------------------------------------------
__global__ void __launch_bounds__(256)
round_tf32(const float* __restrict__ in, float* __restrict__ out, int n4)
{
    const int i = blockIdx.x * 256 + threadIdx.x;
    if (i < n4) {
        float4 v = ((const float4*)in)[i];
        v.x = __uint_as_float(f2tf32(v.x));
        v.y = __uint_as_float(f2tf32(v.y));
        v.z = __uint_as_float(f2tf32(v.z));
        v.w = __uint_as_float(f2tf32(v.w));
        ((float4*)out)[i] = v;
    }
}

// ---------------------------------------------------------------------------
// Pipelined TF32 GEMM body. A and W are PRE-ROUNDED to tf32 values (fp32 bits).
// BK=32, 3-stage cp.async pipeline. No cvt in mainloop.
// EPI: 0 = bias only, 1 = bias + exact GeLU (+ tf32-rounded output),
//      2 = bias + residual add
// ---------------------------------------------------------------------------
constexpr int ASZ = 128 * 36;
constexpr int BSZ = 32 * 136;
constexpr int GEMM_SMEM = 3 * (ASZ + BSZ) * 4;   // 107,520 B

template <int EPI>
__device__ __forceinline__ void gemm_body(
    const float* __restrict__ A, const float* __restrict__ W,
    const float* __restrict__ bias, const float* __restrict__ res,
    float* __restrict__ C, int K, int N, int bx, int by, float* sm)
{
    float* AsB = sm;
    float* BsB = sm + 3 * ASZ;

    const int tid  = threadIdx.x;
    const int lane = tid & 31;
    const int warp = tid >> 5;
    const int g    = lane >> 2;
    const int t    = lane & 3;
    const int wm   = (warp & 1) * 64;
    const int wn   = (warp >> 1) * 32;

    const float* Ab = A + (size_t)(by * 128) * K;
    const float* Wb = W + bx * 128;

    float acc[4][4][4];
#pragma unroll
    for (int mi = 0; mi < 4; mi++)
#pragma unroll
        for (int nj = 0; nj < 4; nj++)
#pragma unroll
            for (int c = 0; c < 4; c++) acc[mi][nj][c] = 0.f;

    auto stage = [&](int buf, int kk) {
        float* Ad = AsB + buf * ASZ;
        float* Bd = BsB + buf * BSZ;
#pragma unroll
        for (int u = 0; u < 4; u++) {
            const int i   = tid + u * 256;
            const int row = i >> 3;
            const int c4  = (i & 7) * 4;
            cp_async16(Ad + row * 36 + c4, Ab + (size_t)row * K + kk + c4);
        }
#pragma unroll
        for (int u = 0; u < 4; u++) {
            const int i   = tid + u * 256;
            const int row = i >> 5;
            const int c4  = (i & 31) * 4;
            cp_async16(Bd + row * 136 + c4, Wb + (size_t)(kk + row) * N + c4);
        }
        cp_commit();
    };

    const int nT = K >> 5;
    stage(0, 0);
    if (nT > 1) stage(1, 32);

    for (int tt = 0; tt < nT; tt++) {
        if (tt + 1 < nT) cp_wait<1>(); else cp_wait<0>();
        __syncthreads();
        if (tt + 2 < nT) stage((tt + 2) % 3, (tt + 2) * 32);

        const uint32_t* Ac = (const uint32_t*)(AsB + (tt % 3) * ASZ);
        const uint32_t* Bc = (const uint32_t*)(BsB + (tt % 3) * BSZ);
#pragma unroll
        for (int ks = 0; ks < 4; ks++) {
            const int kb = ks * 8;
            uint32_t a[4][4], b[4][2];
#pragma unroll
            for (int mi = 0; mi < 4; mi++) {
                const int m0 = wm + mi * 16;
                a[mi][0] = Ac[(m0 + g)     * 36 + kb + t];
                a[mi][1] = Ac[(m0 + 8 + g) * 36 + kb + t];
                a[mi][2] = Ac[(m0 + g)     * 36 + kb + 4 + t];
                a[mi][3] = Ac[(m0 + 8 + g) * 36 + kb + 4 + t];
            }
#pragma unroll
            for (int nj = 0; nj < 4; nj++) {
                const int n0 = wn + nj * 8;
                b[nj][0] = Bc[(kb + t)     * 136 + n0 + g];
                b[nj][1] = Bc[(kb + 4 + t) * 136 + n0 + g];
            }
#pragma unroll
            for (int mi = 0; mi < 4; mi++)
#pragma unroll
                for (int nj = 0; nj < 4; nj++)
                    mma_tf32(acc[mi][nj], a[mi], b[nj]);
        }
    }

    // epilogue
#pragma unroll
    for (int mi = 0; mi < 4; mi++) {
#pragma unroll
        for (int nj = 0; nj < 4; nj++) {
            const int row = by * 128 + wm + mi * 16 + g;
            const int col = bx * 128 + wn + nj * 8 + t * 2;
#pragma unroll
            for (int half = 0; half < 2; half++) {
                const int r = row + half * 8;
                float v0 = acc[mi][nj][half * 2 + 0] + bias[col];
                float v1 = acc[mi][nj][half * 2 + 1] + bias[col + 1];
                if (EPI == 1) {
                    v0 = 0.5f * v0 * (1.0f + erff(v0 * 0.70710678118654752f));
                    v1 = 0.5f * v1 * (1.0f + erff(v1 * 0.70710678118654752f));
                    // round: this output is consumed only as FFN2's A operand
                    v0 = __uint_as_float(f2tf32(v0));
                    v1 = __uint_as_float(f2tf32(v1));
                } else if (EPI == 2) {
                    v0 += res[(size_t)r * N + col];
                    v1 += res[(size_t)r * N + col + 1];
                }
                float2 out = make_float2(v0, v1);
                *(float2*)(C + (size_t)r * N + col) = out;
            }
        }
    }
}

// Fused QKV: blockIdx.z selects {q,k,v}
__global__ void __launch_bounds__(256, 2)
gemm_qkv(const float* __restrict__ x,
         const float* __restrict__ wq, const float* __restrict__ bq,
         const float* __restrict__ wk, const float* __restrict__ bk,
         const float* __restrict__ wv, const float* __restrict__ bv,
         float* __restrict__ q, float* __restrict__ k, float* __restrict__ v)
{
    extern __shared__ float sm[];
    const float* W; const float* bias; float* C;
    if (blockIdx.z == 0)      { W = wq; bias = bq; C = q; }
    else if (blockIdx.z == 1) { W = wk; bias = bk; C = k; }
    else                      { W = wv; bias = bv; C = v; }
    gemm_body<0>(x, W, bias, nullptr, C, D, D, blockIdx.x, blockIdx.y, sm);
}

template <int EPI>
__global__ void __launch_bounds__(256, 2)
gemm_pipe(const float* __restrict__ A, const float* __restrict__ W,
          const float* __restrict__ bias, const float* __restrict__ res,
          float* __restrict__ C, int K, int N)
{
    extern __shared__ float sm[];
    gemm_body<EPI>(A, W, bias, res, C, K, N, blockIdx.x, blockIdx.y, sm);
}

// ---------------------------------------------------------------------------
// Flash attention (unchanged from round 4/5)
// ---------------------------------------------------------------------------
constexpr int PS_STRIDE = 132;
constexpr int KS_STRIDE = 68;
constexpr int VS_STRIDE = 72;
constexpr int ATTN_SMEM = (128 * PS_STRIDE + 128 * KS_STRIDE + 128 * VS_STRIDE) * 4;

__global__ void __launch_bounds__(256)
flash_attn(const float* __restrict__ Q, const float* __restrict__ Kg,
           const float* __restrict__ Vg, float* __restrict__ O)
{
    extern __shared__ uint32_t smem[];
    uint32_t* Ps = smem;
    uint32_t* Ks = Ps + 128 * PS_STRIDE;
    uint32_t* Vs = Ks + 128 * KS_STRIDE;

    const int tid  = threadIdx.x;
    const int lane = tid & 31;
    const int warp = tid >> 5;
    const int g    = lane >> 2;
    const int t    = lane & 3;
    const int m0   = warp * 16;

    const int q0 = blockIdx.x * 128;
    const int h  = blockIdx.y;
    const int b  = blockIdx.z;

    const float* Qb = Q  + (size_t)b * S * D + h * DK;
    const float* Kb = Kg + (size_t)b * S * D + h * DK;
    const float* Vb = Vg + (size_t)b * S * D + h * DK;

#pragma unroll
    for (int u = 0; u < 8; u++) {
        const int idx = u * 256 + tid;
        const int row = idx >> 4;
        const int c4  = (idx & 15) * 4;
        float4 v = *(const float4*)(Qb + (size_t)(q0 + row) * D + c4);
        Ps[row * PS_STRIDE + c4 + 0] = f2tf32(v.x * 0.125f);
        Ps[row * PS_STRIDE + c4 + 1] = f2tf32(v.y * 0.125f);
        Ps[row * PS_STRIDE + c4 + 2] = f2tf32(v.z * 0.125f);
        Ps[row * PS_STRIDE + c4 + 3] = f2tf32(v.w * 0.125f);
    }
    __syncthreads();

    uint32_t qf[8][4];
#pragma unroll
    for (int kc = 0; kc < 8; kc++) {
        const int kb = kc * 8;
        qf[kc][0] = Ps[(m0 + g)     * PS_STRIDE + kb + t];
        qf[kc][1] = Ps[(m0 + 8 + g) * PS_STRIDE + kb + t];
        qf[kc][2] = Ps[(m0 + g)     * PS_STRIDE + kb + 4 + t];
        qf[kc][3] = Ps[(m0 + 8 + g) * PS_STRIDE + kb + 4 + t];
    }

    float o[8][4];
#pragma unroll
    for (int j = 0; j < 8; j++)
#pragma unroll
        for (int c = 0; c < 4; c++) o[j][c] = 0.f;
    float mrun0 = -1e30f, mrun1 = -1e30f, lrun0 = 0.f, lrun1 = 0.f;

    for (int k0 = 0; k0 < S; k0 += 128) {
        __syncthreads();
#pragma unroll
        for (int u = 0; u < 8; u++) {
            const int idx = u * 256 + tid;
            const int row = idx >> 4;
            const int c4  = (idx & 15) * 4;
            float4 kv = *(const float4*)(Kb + (size_t)(k0 + row) * D + c4);
            Ks[row * KS_STRIDE + c4 + 0] = f2tf32(kv.x);
            Ks[row * KS_STRIDE + c4 + 1] = f2tf32(kv.y);
            Ks[row * KS_STRIDE + c4 + 2] = f2tf32(kv.z);
            Ks[row * KS_STRIDE + c4 + 3] = f2tf32(kv.w);
            float4 vv = *(const float4*)(Vb + (size_t)(k0 + row) * D + c4);
            Vs[row * VS_STRIDE + c4 + 0] = f2tf32(vv.x);
            Vs[row * VS_STRIDE + c4 + 1] = f2tf32(vv.y);
            Vs[row * VS_STRIDE + c4 + 2] = f2tf32(vv.z);
            Vs[row * VS_STRIDE + c4 + 3] = f2tf32(vv.w);
        }
        __syncthreads();

        float sc[16][4];
#pragma unroll
        for (int j = 0; j < 16; j++) {
            sc[j][0] = 0.f; sc[j][1] = 0.f; sc[j][2] = 0.f; sc[j][3] = 0.f;
            const int n0 = j * 8;
#pragma unroll
            for (int kc = 0; kc < 8; kc++) {
                const int kb = kc * 8;
                uint32_t bf[2];
                bf[0] = Ks[(n0 + g) * KS_STRIDE + kb + t];
                bf[1] = Ks[(n0 + g) * KS_STRIDE + kb + 4 + t];
                mma_tf32(sc[j], qf[kc], bf);
            }
        }

        float nm0 = -1e30f, nm1 = -1e30f;
#pragma unroll
        for (int j = 0; j < 16; j++) {
            nm0 = fmaxf(nm0, fmaxf(sc[j][0], sc[j][1]));
            nm1 = fmaxf(nm1, fmaxf(sc[j][2], sc[j][3]));
        }
        nm0 = fmaxf(nm0, __shfl_xor_sync(0xffffffffu, nm0, 1));
        nm0 = fmaxf(nm0, __shfl_xor_sync(0xffffffffu, nm0, 2));
        nm1 = fmaxf(nm1, __shfl_xor_sync(0xffffffffu, nm1, 1));
        nm1 = fmaxf(nm1, __shfl_xor_sync(0xffffffffu, nm1, 2));
        const float newm0 = fmaxf(mrun0, nm0);
        const float newm1 = fmaxf(mrun1, nm1);
        const float f0 = __expf(mrun0 - newm0);
        const float f1 = __expf(mrun1 - newm1);

        float s0 = 0.f, s1 = 0.f;
#pragma unroll
        for (int j = 0; j < 16; j++) {
            const float p00 = __expf(sc[j][0] - newm0);
            const float p01 = __expf(sc[j][1] - newm0);
            const float p10 = __expf(sc[j][2] - newm1);
            const float p11 = __expf(sc[j][3] - newm1);
            s0 += p00 + p01;
            s1 += p10 + p11;
            uint2 w0 = make_uint2(f2tf32(p00), f2tf32(p01));
            uint2 w1 = make_uint2(f2tf32(p10), f2tf32(p11));
            *(uint2*)&Ps[(m0 + g)     * PS_STRIDE + j * 8 + 2 * t] = w0;
            *(uint2*)&Ps[(m0 + 8 + g) * PS_STRIDE + j * 8 + 2 * t] = w1;
        }
        s0 += __shfl_xor_sync(0xffffffffu, s0, 1);
        s0 += __shfl_xor_sync(0xffffffffu, s0, 2);
        s1 += __shfl_xor_sync(0xffffffffu, s1, 1);
        s1 += __shfl_xor_sync(0xffffffffu, s1, 2);
        lrun0 = lrun0 * f0 + s0;
        lrun1 = lrun1 * f1 + s1;
        mrun0 = newm0;
        mrun1 = newm1;
#pragma unroll
        for (int j = 0; j < 8; j++) {
            o[j][0] *= f0; o[j][1] *= f0;
            o[j][2] *= f1; o[j][3] *= f1;
        }
        __syncwarp();

#pragma unroll
        for (int kc = 0; kc < 16; kc++) {
            const int kb = kc * 8;
            uint32_t a[4];
            a[0] = Ps[(m0 + g)     * PS_STRIDE + kb + t];
            a[1] = Ps[(m0 + 8 + g) * PS_STRIDE + kb + t];
            a[2] = Ps[(m0 + g)     * PS_STRIDE + kb + 4 + t];
            a[3] = Ps[(m0 + 8 + g) * PS_STRIDE + kb + 4 + t];
#pragma unroll
            for (int j = 0; j < 8; j++) {
                uint32_t bf[2];
                bf[0] = Vs[(kb + t)     * VS_STRIDE + j * 8 + g];
                bf[1] = Vs[(kb + 4 + t) * VS_STRIDE + j * 8 + g];
                mma_tf32(o[j], a, bf);
            }
        }
    }

    const float inv0 = 1.0f / lrun0;
    const float inv1 = 1.0f / lrun1;
    const int row0 = q0 + m0 + g;
    const int row1 = row0 + 8;
#pragma unroll
    for (int j = 0; j < 8; j++) {
        const int col = h * DK + j * 8 + 2 * t;
        float2 r0 = make_float2(o[j][0] * inv0, o[j][1] * inv0);
        float2 r1 = make_float2(o[j][2] * inv1, o[j][3] * inv1);
        *(float2*)(O + (size_t)(b * S + row0) * D + col) = r0;
        *(float2*)(O + (size_t)(b * S + row1) * D + col) = r1;
    }
}

// ---------------------------------------------------------------------------
// LayerNorm over (S,D) per batch
// ---------------------------------------------------------------------------
__global__ void __launch_bounds__(256)
ln_partial(const float* __restrict__ a, const float* __restrict__ c,
           float* __restrict__ y, float* __restrict__ part)
{
    const int b = blockIdx.y, chunk = blockIdx.x, tid = threadIdx.x;
    const size_t base = (size_t)b * S * D + (size_t)chunk * 4096 + tid * 16;
    float s = 0.f, s2 = 0.f;
#pragma unroll
    for (int i = 0; i < 16; i += 4) {
        float4 va = *(const float4*)(a + base + i);
        if (c) {
            float4 vc = *(const float4*)(c + base + i);
            va.x += vc.x; va.y += vc.y; va.z += vc.z; va.w += vc.w;
        }
        if (y) *(float4*)(y + base + i) = va;
        s  += va.x + va.y + va.z + va.w;
        s2 += va.x * va.x + va.y * va.y + va.z * va.z + va.w * va.w;
    }
    __shared__ float r1[256], r2[256];
    r1[tid] = s; r2[tid] = s2; __syncthreads();
    for (int st = 128; st > 0; st >>= 1) {
        if (tid < st) { r1[tid] += r1[tid + st]; r2[tid] += r2[tid + st]; }
        __syncthreads();
    }
    if (tid == 0) {
        part[b * 256 + chunk]            = r1[0];
        part[B * 256 + b * 256 + chunk]  = r2[0];
    }
}

__global__ void __launch_bounds__(256)
ln_finalize(const float* __restrict__ part, float* __restrict__ stats)
{
    const int b = blockIdx.x, tid = threadIdx.x;
    __shared__ float r1[256], r2[256];
    r1[tid] = part[b * 256 + tid];
    r2[tid] = part[B * 256 + b * 256 + tid];
    __syncthreads();
    for (int st = 128; st > 0; st >>= 1) {
        if (tid < st) { r1[tid] += r1[tid + st]; r2[tid] += r2[tid + st]; }
        __syncthreads();
    }
    if (tid == 0) {
        const float n = (float)S * (float)D;
        float mean = r1[0] / n;
        float var  = r2[0] / n - mean * mean;
        stats[2 * b]     = mean;
        stats[2 * b + 1] = rsqrtf(var + EPS);
    }
}

// normalize + affine; optionally emit tf32-rounded copy (for GEMM A operand)
__global__ void __launch_bounds__(256)
ln_apply(const float* __restrict__ y, const float* __restrict__ g,
         const float* __restrict__ beta, const float* __restrict__ stats,
         float* __restrict__ out, float* __restrict__ out_r)
{
    const int b = blockIdx.y;
    const int idx = (blockIdx.x * 256 + threadIdx.x) * 4;
    const float mean = stats[2 * b];
    const float rstd = stats[2 * b + 1];
    const size_t off = (size_t)b * S * D + idx;
    float4 v  = *(const float4*)(y + off);
    float4 gg = *(const float4*)(g + idx);
    float4 bb = *(const float4*)(beta + idx);
    v.x = (v.x - mean) * rstd * gg.x + bb.x;
    v.y = (v.y - mean) * rstd * gg.y + bb.y;
    v.z = (v.z - mean) * rstd * gg.z + bb.z;
    v.w = (v.w - mean) * rstd * gg.w + bb.w;
    *(float4*)(out + off) = v;
    if (out_r) {
        float4 r;
        r.x = __uint_as_float(f2tf32(v.x));
        r.y = __uint_as_float(f2tf32(v.y));
        r.z = __uint_as_float(f2tf32(v.z));
        r.w = __uint_as_float(f2tf32(v.w));
        *(float4*)(out_r + off) = r;
    }
}

// ---------------------------------------------------------------------------
// kernel_launch
// ---------------------------------------------------------------------------
extern "C" void kernel_launch(void* const* d_in, const int* in_sizes, int n_in,
                              void* d_out, int out_size)
{
    const float* x    = (const float*)d_in[0];
    const float* wq   = (const float*)d_in[1];
    const float* bq   = (const float*)d_in[2];
    const float* wk   = (const float*)d_in[3];
    const float* bk   = (const float*)d_in[4];
    const float* wv   = (const float*)d_in[5];
    const float* bv   = (const float*)d_in[6];
    const float* ln1g = (const float*)d_in[7];
    const float* ln1b = (const float*)d_in[8];
    const float* w1   = (const float*)d_in[9];
    const float* b1   = (const float*)d_in[10];
    const float* w2   = (const float*)d_in[11];
    const float* b2   = (const float*)d_in[12];
    const float* ln2g = (const float*)d_in[13];
    const float* ln2b = (const float*)d_in[14];
    float* out = (float*)d_out;

    float *q, *k, *v, *ctx, *h, *ff, *part, *stats;
    float *xr, *hr, *wqr, *wkr, *wvr, *w1r, *w2r;
    cudaGetSymbolAddress((void**)&q,     g_q);
    cudaGetSymbolAddress((void**)&k,     g_k);
    cudaGetSymbolAddress((void**)&v,     g_v);
    cudaGetSymbolAddress((void**)&ctx,   g_ctx);
    cudaGetSymbolAddress((void**)&h,     g_h);
    cudaGetSymbolAddress((void**)&ff,    g_ff);
    cudaGetSymbolAddress((void**)&part,  g_part);
    cudaGetSymbolAddress((void**)&stats, g_stats);
    cudaGetSymbolAddress((void**)&xr,    g_xr);
    cudaGetSymbolAddress((void**)&hr,    g_hr);
    cudaGetSymbolAddress((void**)&wqr,   g_wqr);
    cudaGetSymbolAddress((void**)&wkr,   g_wkr);
    cudaGetSymbolAddress((void**)&wvr,   g_wvr);
    cudaGetSymbolAddress((void**)&w1r,   g_w1r);
    cudaGetSymbolAddress((void**)&w2r,   g_w2r);

    static bool attr_done = false;
    if (!attr_done) {
        cudaFuncSetAttribute(flash_attn,
                             cudaFuncAttributeMaxDynamicSharedMemorySize, ATTN_SMEM);
        cudaFuncSetAttribute(gemm_qkv,
                             cudaFuncAttributeMaxDynamicSharedMemorySize, GEMM_SMEM);
        cudaFuncSetAttribute(gemm_pipe<1>,
                             cudaFuncAttributeMaxDynamicSharedMemorySize, GEMM_SMEM);
        cudaFuncSetAttribute(gemm_pipe<2>,
                             cudaFuncAttributeMaxDynamicSharedMemorySize, GEMM_SMEM);
        attr_done = true;
    }

    // tf32 pre-rounding of GEMM operands
    round_tf32<<<(NT * D / 4 + 255) / 256, 256>>>(x,  xr,  NT * D / 4);
    round_tf32<<<(D * D / 4 + 255) / 256, 256>>>(wq, wqr, D * D / 4);
    round_tf32<<<(D * D / 4 + 255) / 256, 256>>>(wk, wkr, D * D / 4);
    round_tf32<<<(D * D / 4 + 255) / 256, 256>>>(wv, wvr, D * D / 4);
    round_tf32<<<(D * DFF / 4 + 255) / 256, 256>>>(w1, w1r, D * DFF / 4);
    round_tf32<<<(D * DFF / 4 + 255) / 256, 256>>>(w2, w2r, D * DFF / 4);

    // QKV projections (fused launch, pre-rounded operands)
    gemm_qkv<<<dim3(D / 128, NT / 128, 3), 256, GEMM_SMEM>>>(
        xr, wqr, bq, wkr, bk, wvr, bv, q, k, v);

    // Flash attention
    flash_attn<<<dim3(S / 128, H, B), 256, ATTN_SMEM>>>(q, k, v, ctx);

    // LayerNorm 1: h = LN(x + ctx) (+ rounded copy hr)
    ln_partial<<<dim3(256, B), 256>>>(x, ctx, h, part);
    ln_finalize<<<B, 256>>>(part, stats);
    ln_apply<<<dim3(1024, B), 256>>>(h, ln1g, ln1b, stats, h, hr);

    // FFN: ff = round(gelu(hr @ w1r + b1)); ctx = ff @ w2r + b2 + h
    gemm_pipe<1><<<dim3(DFF / 128, NT / 128), 256, GEMM_SMEM>>>(hr, w1r, b1, nullptr, ff, D, DFF);
    gemm_pipe<2><<<dim3(D / 128, NT / 128), 256, GEMM_SMEM>>>(ff, w2r, b2, h, ctx, DFF, D);

    // LayerNorm 2 -> output
    ln_partial<<<dim3(256, B), 256>>>(ctx, nullptr, nullptr, part);
    ln_finalize<<<B, 256>>>(part, stats);
    ln_apply<<<dim3(1024, B), 256>>>(ctx, ln2g, ln2b, stats, out, nullptr);
}